// round 8
// baseline (speedup 1.0000x reference)
#include <cuda_runtime.h>
#include <cuda.h>
#include <cuda_bf16.h>
#include <cstdint>

#define EMBED    1024
#define HEADS    16
#define HEAD_DIM 64
#define SEQ      2048
#define BATCH    2
#define MTOT     (BATCH * SEQ)    // 4096

// ------------------------------ scratch (TMA needs alignment) ---------------
__device__ __align__(1024) __nv_bfloat16 g_xhi[(size_t)MTOT * EMBED];
__device__ __align__(1024) __nv_bfloat16 g_xlo[(size_t)MTOT * EMBED];
__device__ __align__(1024) __nv_bfloat16 g_wqh[(size_t)3 * EMBED * EMBED];
__device__ __align__(1024) __nv_bfloat16 g_wql[(size_t)3 * EMBED * EMBED];
__device__ __align__(1024) __nv_bfloat16 g_wph[(size_t)EMBED * EMBED];
__device__ __align__(1024) __nv_bfloat16 g_wpl[(size_t)EMBED * EMBED];
__device__ __align__(1024) __nv_bfloat16 g_qh[(size_t)MTOT * 3 * EMBED];
__device__ __align__(1024) __nv_bfloat16 g_ql[(size_t)MTOT * 3 * EMBED];
__device__ __align__(1024) __nv_bfloat16 g_ahi[(size_t)MTOT * EMBED];
__device__ __align__(1024) __nv_bfloat16 g_alo[(size_t)MTOT * EMBED];

// --------------------------- PTX helpers ------------------------------------
__device__ __forceinline__ uint32_t smem_u32(const void* p) {
    uint32_t a;
    asm("{ .reg .u64 t; cvta.to.shared.u64 t, %1; cvt.u32.u64 %0, t; }" : "=r"(a) : "l"(p));
    return a;
}
__device__ __forceinline__ void ldsm4(uint32_t* a, uint32_t addr) {
    asm volatile("ldmatrix.sync.aligned.m8n8.x4.shared.b16 {%0,%1,%2,%3}, [%4];"
                 : "=r"(a[0]), "=r"(a[1]), "=r"(a[2]), "=r"(a[3]) : "r"(addr));
}
__device__ __forceinline__ void ldsm2(uint32_t* b, uint32_t addr) {
    asm volatile("ldmatrix.sync.aligned.m8n8.x2.shared.b16 {%0,%1}, [%2];"
                 : "=r"(b[0]), "=r"(b[1]) : "r"(addr));
}
__device__ __forceinline__ void ldsm2t(uint32_t* b, uint32_t addr) {
    asm volatile("ldmatrix.sync.aligned.m8n8.x2.trans.shared.b16 {%0,%1}, [%2];"
                 : "=r"(b[0]), "=r"(b[1]) : "r"(addr));
}
__device__ __forceinline__ void mma16816(float* c, const uint32_t* a, const uint32_t* b) {
    asm volatile(
        "mma.sync.aligned.m16n8k16.row.col.f32.bf16.bf16.f32 "
        "{%0,%1,%2,%3},{%4,%5,%6,%7},{%8,%9},{%0,%1,%2,%3};"
        : "+f"(c[0]), "+f"(c[1]), "+f"(c[2]), "+f"(c[3])
        : "r"(a[0]), "r"(a[1]), "r"(a[2]), "r"(a[3]), "r"(b[0]), "r"(b[1]));
}
__device__ __forceinline__ void tma2d(uint32_t s, const CUtensorMap* m, int x, int y, uint32_t mb) {
    asm volatile(
        "cp.async.bulk.tensor.2d.shared::cta.global.tile.mbarrier::complete_tx::bytes "
        "[%0], [%1, {%2, %3}], [%4];"
        :: "r"(s), "l"(m), "r"(x), "r"(y), "r"(mb) : "memory");
}
__device__ __forceinline__ void mb_init(uint32_t mb, uint32_t cnt) {
    asm volatile("mbarrier.init.shared.b64 [%0], %1;" :: "r"(mb), "r"(cnt) : "memory");
}
__device__ __forceinline__ void mb_expect(uint32_t mb, uint32_t bytes) {
    asm volatile("mbarrier.arrive.expect_tx.shared.b64 _, [%0], %1;" :: "r"(mb), "r"(bytes) : "memory");
}
#define MBWAIT(mb, ph)                                                          \
    asm volatile("{\n .reg .pred p;\nWL%=:\n"                                   \
                 " mbarrier.try_wait.parity.shared.b64 p, [%0], %1;\n"          \
                 " @!p bra WL%=;\n}"                                            \
                 :: "r"(mb), "r"((uint32_t)(ph)) : "memory")

__device__ __forceinline__ uint32_t pack2(float a, float b) {
    __nv_bfloat162 t = __floats2bfloat162_rn(a, b);
    return *(uint32_t*)&t;
}
__device__ __forceinline__ void split2(float a, float b, uint32_t& H, uint32_t& L) {
    __nv_bfloat16 ha = __float2bfloat16(a), hb = __float2bfloat16(b);
    float la = a - __bfloat162float(ha), lb = b - __bfloat162float(hb);
    H = ((uint32_t)__bfloat16_as_ushort(hb) << 16) | __bfloat16_as_ushort(ha);
    L = pack2(la, lb);
}

// -------------- fp32 -> (bf16 hi, bf16 lo), 3 tensors in one launch ---------
#define N4_X  (MTOT * EMBED / 4)
#define N4_WQ (3 * EMBED * EMBED / 4)
#define N4_WP (EMBED * EMBED / 4)

__global__ __launch_bounds__(256)
void split3_kernel(const float* __restrict__ x,  __nv_bfloat16* __restrict__ xh, __nv_bfloat16* __restrict__ xl,
                   const float* __restrict__ wq, __nv_bfloat16* __restrict__ qh, __nv_bfloat16* __restrict__ ql,
                   const float* __restrict__ wp, __nv_bfloat16* __restrict__ ph, __nv_bfloat16* __restrict__ pl)
{
    int i = blockIdx.x * blockDim.x + threadIdx.x;
    const float* in; __nv_bfloat16 *hi, *lo;
    if (i < N4_X)                { in = x;  hi = xh; lo = xl; }
    else if (i < N4_X + N4_WQ)   { in = wq; hi = qh; lo = ql; i -= N4_X; }
    else if (i < N4_X + N4_WQ + N4_WP) { in = wp; hi = ph; lo = pl; i -= N4_X + N4_WQ; }
    else return;
    float4 v = ((const float4*)in)[i];
    uint2 H, L;
    split2(v.x, v.y, H.x, L.x);
    split2(v.z, v.w, H.y, L.y);
    ((uint2*)hi)[i] = H;
    ((uint2*)lo)[i] = L;
}

// ----------- TMA + mma.sync bf16x3 GEMM: C = A W^T + bias -------------------
// BK=64, 3-stage TMA pipeline, SW128 swizzle, 512 threads / 16 warps,
// warp tile 32x32 -> 4 warps per SMSP for latency hiding.
#define GSTG 65536                       // 4 tiles x 16KB per stage
#define GSM  (1024 + 3 * GSTG)

template<int MODE>
__global__ __launch_bounds__(512)
void gemm_tma(const __grid_constant__ CUtensorMap mAh,
              const __grid_constant__ CUtensorMap mAl,
              const __grid_constant__ CUtensorMap mBh,
              const __grid_constant__ CUtensorMap mBl,
              const float* __restrict__ bias, float* __restrict__ C,
              __nv_bfloat16* __restrict__ Chi, __nv_bfloat16* __restrict__ Clo,
              int M, int N, int K)
{
    extern __shared__ char smem[];
    __shared__ uint64_t mbar[3];
    const uint32_t sb0 = (smem_u32(smem) + 1023) & ~1023u;

    const int t = threadIdx.x, lane = t & 31, wid = t >> 5;
    const int row0 = blockIdx.y * 128, col0 = blockIdx.x * 128;
    const int m0 = (wid >> 2) * 32, n0 = (wid & 3) * 32;

    uint32_t mb[3];
    #pragma unroll
    for (int s = 0; s < 3; s++) mb[s] = smem_u32(&mbar[s]);
    if (t == 0) {
        #pragma unroll
        for (int s = 0; s < 3; s++) mb_init(mb[s], 1);
    }
    __syncthreads();

    auto issue = [&](int kt) {
        const int s = kt % 3;
        const uint32_t base = sb0 + s * GSTG;
        mb_expect(mb[s], GSTG);
        tma2d(base,         &mAh, kt * 64, row0, mb[s]);
        tma2d(base + 16384, &mAl, kt * 64, row0, mb[s]);
        tma2d(base + 32768, &mBh, kt * 64, col0, mb[s]);
        tma2d(base + 49152, &mBl, kt * 64, col0, mb[s]);
    };
    if (t == 0) { issue(0); issue(1); }

    float c[2][4][4] = {};
    const int KT = K / 64;

    for (int kt = 0; kt < KT; kt++) {
        if (t == 0 && kt + 2 < KT) issue(kt + 2);
        const int s = kt % 3;
        MBWAIT(mb[s], (kt / 3) & 1);
        const uint32_t base = sb0 + s * GSTG;
        const uint32_t aAh = base, aAl = base + 16384, aBh = base + 32768, aBl = base + 49152;

        #pragma unroll
        for (int ks = 0; ks < 4; ks++) {
            uint32_t ad[2], bd[4];
            #pragma unroll
            for (int i = 0; i < 2; i++) {
                const int r = m0 + (lane & 15) + i * 16;
                const int ch = 2 * ks + (lane >> 4);
                ad[i] = (uint32_t)(r * 128 + ((ch ^ (r & 7)) << 4));
            }
            #pragma unroll
            for (int j = 0; j < 4; j++) {
                const int r = n0 + (lane & 7) + j * 8;
                const int ch = 2 * ks + ((lane >> 3) & 1);
                bd[j] = (uint32_t)(r * 128 + ((ch ^ (r & 7)) << 4));
            }
            uint32_t ah[2][4], al[2][4], bh[4][2], bl[4][2];
            #pragma unroll
            for (int i = 0; i < 2; i++) ldsm4(ah[i], aAh + ad[i]);
            #pragma unroll
            for (int j = 0; j < 4; j++) ldsm2(bh[j], aBh + bd[j]);
            #pragma unroll
            for (int i = 0; i < 2; i++)
                #pragma unroll
                for (int j = 0; j < 4; j++) mma16816(c[i][j], ah[i], bh[j]);
            #pragma unroll
            for (int j = 0; j < 4; j++) ldsm2(bl[j], aBl + bd[j]);
            #pragma unroll
            for (int i = 0; i < 2; i++)
                #pragma unroll
                for (int j = 0; j < 4; j++) mma16816(c[i][j], ah[i], bl[j]);
            #pragma unroll
            for (int i = 0; i < 2; i++) ldsm4(al[i], aAl + ad[i]);
            #pragma unroll
            for (int i = 0; i < 2; i++)
                #pragma unroll
                for (int j = 0; j < 4; j++) mma16816(c[i][j], al[i], bh[j]);
        }
        __syncthreads();
    }

    #pragma unroll
    for (int j = 0; j < 4; j++) {
        const int col = col0 + n0 + j * 8 + (lane & 3) * 2;
        const float2 bb = *(const float2*)&bias[col];
        const float sc = (MODE == 1 && col < EMBED) ? 0.125f : 1.0f;
        #pragma unroll
        for (int i = 0; i < 2; i++) {
            const int r0 = row0 + m0 + i * 16 + (lane >> 2);
            float v0 = (c[i][j][0] + bb.x) * sc, v1 = (c[i][j][1] + bb.y) * sc;
            float v2 = (c[i][j][2] + bb.x) * sc, v3 = (c[i][j][3] + bb.y) * sc;
            if (MODE == 0) {
                *(float2*)&C[(size_t)r0 * N + col]       = make_float2(v0, v1);
                *(float2*)&C[(size_t)(r0 + 8) * N + col] = make_float2(v2, v3);
            } else {
                uint32_t H, L;
                split2(v0, v1, H, L);
                *(uint32_t*)&Chi[(size_t)r0 * N + col] = H;
                *(uint32_t*)&Clo[(size_t)r0 * N + col] = L;
                split2(v2, v3, H, L);
                *(uint32_t*)&Chi[(size_t)(r0 + 8) * N + col] = H;
                *(uint32_t*)&Clo[(size_t)(r0 + 8) * N + col] = L;
            }
        }
    }
}

// -------------- TMA + mma.sync bf16x3 flash attention (unchanged) -----------
#define ASTG 65536
#define ASM_BYTES (1024 + 2 * 16384 + 2 * ASTG)

__global__ __launch_bounds__(256)
void attn_tma(const __grid_constant__ CUtensorMap mQh,
              const __grid_constant__ CUtensorMap mQl,
              __nv_bfloat16* __restrict__ ohi, __nv_bfloat16* __restrict__ olo)
{
    extern __shared__ char smem[];
    __shared__ uint64_t mbar[3];
    const uint32_t sb0 = (smem_u32(smem) + 1023) & ~1023u;
    const uint32_t sQh = sb0, sQl = sb0 + 16384;
    const uint32_t sKV = sb0 + 32768;

    const int t = threadIdx.x, lane = t & 31, wid = t >> 5;
    const int qt = blockIdx.x, h = blockIdx.y, b = blockIdx.z;
    const int qrow = b * SEQ + qt * 128;

    uint32_t qb = smem_u32(&mbar[0]);
    uint32_t kb[2] = { smem_u32(&mbar[1]), smem_u32(&mbar[2]) };
    if (t == 0) { mb_init(qb, 1); mb_init(kb[0], 1); mb_init(kb[1], 1); }
    __syncthreads();

    auto issueKV = [&](int kt) {
        const int s = kt & 1;
        const uint32_t base = sKV + s * ASTG;
        const int krow = b * SEQ + kt * 128;
        mb_expect(kb[s], ASTG);
        tma2d(base,         &mQh, EMBED + h * HEAD_DIM,     krow, kb[s]);
        tma2d(base + 16384, &mQl, EMBED + h * HEAD_DIM,     krow, kb[s]);
        tma2d(base + 32768, &mQh, 2 * EMBED + h * HEAD_DIM, krow, kb[s]);
        tma2d(base + 49152, &mQl, 2 * EMBED + h * HEAD_DIM, krow, kb[s]);
    };
    if (t == 0) {
        mb_expect(qb, 32768);
        tma2d(sQh, &mQh, h * HEAD_DIM, qrow, qb);
        tma2d(sQl, &mQl, h * HEAD_DIM, qrow, qb);
        issueKV(0);
        issueKV(1);
    }

    uint32_t qfh[4][4], qfl[4][4];
    MBWAIT(qb, 0);
    #pragma unroll
    for (int ks = 0; ks < 4; ks++) {
        const int r = wid * 16 + (lane & 15);
        const int ch = 2 * ks + (lane >> 4);
        const uint32_t qd = (uint32_t)(r * 128 + ((ch ^ (r & 7)) << 4));
        ldsm4(qfh[ks], sQh + qd);
        ldsm4(qfl[ks], sQl + qd);
    }

    float o[8][4] = {};
    float m_lo = -1e30f, m_hi = -1e30f, l_lo = 0.0f, l_hi = 0.0f;

    const int NKV = SEQ / 128;
    for (int kt = 0; kt < NKV; kt++) {
        const int s = kt & 1;
        MBWAIT(kb[s], (kt / 2) & 1);
        const uint32_t base = sKV + s * ASTG;
        const uint32_t aKh = base, aKl = base + 16384, aVh = base + 32768, aVl = base + 49152;

        float sfr[16][4] = {};
        #pragma unroll
        for (int ks = 0; ks < 4; ks++) {
            uint32_t kd[16];
            #pragma unroll
            for (int j = 0; j < 16; j++) {
                const int r = j * 8 + (lane & 7);
                const int ch = 2 * ks + ((lane >> 3) & 1);
                kd[j] = (uint32_t)(r * 128 + ((ch ^ (r & 7)) << 4));
            }
            uint32_t kf[16][2];
            #pragma unroll
            for (int j = 0; j < 16; j++) ldsm2(kf[j], aKh + kd[j]);
            #pragma unroll
            for (int j = 0; j < 16; j++) mma16816(sfr[j], qfh[ks], kf[j]);
            #pragma unroll
            for (int j = 0; j < 16; j++) mma16816(sfr[j], qfl[ks], kf[j]);
            #pragma unroll
            for (int j = 0; j < 16; j++) ldsm2(kf[j], aKl + kd[j]);
            #pragma unroll
            for (int j = 0; j < 16; j++) mma16816(sfr[j], qfh[ks], kf[j]);
        }

        float tmax_lo = -1e30f, tmax_hi = -1e30f;
        #pragma unroll
        for (int j = 0; j < 16; j++) {
            tmax_lo = fmaxf(tmax_lo, fmaxf(sfr[j][0], sfr[j][1]));
            tmax_hi = fmaxf(tmax_hi, fmaxf(sfr[j][2], sfr[j][3]));
        }
        tmax_lo = fmaxf(tmax_lo, __shfl_xor_sync(0xffffffffu, tmax_lo, 1));
        tmax_lo = fmaxf(tmax_lo, __shfl_xor_sync(0xffffffffu, tmax_lo, 2));
        tmax_hi = fmaxf(tmax_hi, __shfl_xor_sync(0xffffffffu, tmax_hi, 1));
        tmax_hi = fmaxf(tmax_hi, __shfl_xor_sync(0xffffffffu, tmax_hi, 2));
        float mn_lo = fmaxf(m_lo, tmax_lo), mn_hi = fmaxf(m_hi, tmax_hi);
        float corr_lo = __expf(m_lo - mn_lo), corr_hi = __expf(m_hi - mn_hi);
        m_lo = mn_lo; m_hi = mn_hi;

        float sum_lo = 0.0f, sum_hi = 0.0f;
        #pragma unroll
        for (int j = 0; j < 16; j++) {
            sfr[j][0] = __expf(sfr[j][0] - m_lo); sfr[j][1] = __expf(sfr[j][1] - m_lo);
            sfr[j][2] = __expf(sfr[j][2] - m_hi); sfr[j][3] = __expf(sfr[j][3] - m_hi);
            sum_lo += sfr[j][0] + sfr[j][1];
            sum_hi += sfr[j][2] + sfr[j][3];
        }
        sum_lo += __shfl_xor_sync(0xffffffffu, sum_lo, 1);
        sum_lo += __shfl_xor_sync(0xffffffffu, sum_lo, 2);
        sum_hi += __shfl_xor_sync(0xffffffffu, sum_hi, 1);
        sum_hi += __shfl_xor_sync(0xffffffffu, sum_hi, 2);
        l_lo = l_lo * corr_lo + sum_lo;
        l_hi = l_hi * corr_hi + sum_hi;
        #pragma unroll
        for (int j = 0; j < 8; j++) {
            o[j][0] *= corr_lo; o[j][1] *= corr_lo;
            o[j][2] *= corr_hi; o[j][3] *= corr_hi;
        }

        #pragma unroll
        for (int kk = 0; kk < 8; kk++) {
            uint32_t ph[4], pl[4];
            split2(sfr[2*kk  ][0], sfr[2*kk  ][1], ph[0], pl[0]);
            split2(sfr[2*kk  ][2], sfr[2*kk  ][3], ph[1], pl[1]);
            split2(sfr[2*kk+1][0], sfr[2*kk+1][1], ph[2], pl[2]);
            split2(sfr[2*kk+1][2], sfr[2*kk+1][3], ph[3], pl[3]);

            const int r = kk * 16 + (lane & 15);
            uint32_t vf[8][2];
            #pragma unroll
            for (int j = 0; j < 8; j++)
                ldsm2t(vf[j], aVh + (uint32_t)(r * 128 + ((j ^ (r & 7)) << 4)));
            #pragma unroll
            for (int j = 0; j < 8; j++) mma16816(o[j], ph, vf[j]);
            #pragma unroll
            for (int j = 0; j < 8; j++) mma16816(o[j], pl, vf[j]);
            #pragma unroll
            for (int j = 0; j < 8; j++)
                ldsm2t(vf[j], aVl + (uint32_t)(r * 128 + ((j ^ (r & 7)) << 4)));
            #pragma unroll
            for (int j = 0; j < 8; j++) mma16816(o[j], ph, vf[j]);
        }
        __syncthreads();
        if (t == 0 && kt + 2 < NKV) issueKV(kt + 2);
    }

    const float inv_lo = 1.0f / l_lo, inv_hi = 1.0f / l_hi;
    const int r_lo = qt * 128 + wid * 16 + (lane >> 2);
    const size_t obase = (size_t)(b * SEQ) * EMBED + (size_t)h * HEAD_DIM;
    #pragma unroll
    for (int j = 0; j < 8; j++) {
        const int col = j * 8 + (lane & 3) * 2;
        uint32_t H, L;
        split2(o[j][0] * inv_lo, o[j][1] * inv_lo, H, L);
        *(uint32_t*)&ohi[obase + (size_t)r_lo * EMBED + col] = H;
        *(uint32_t*)&olo[obase + (size_t)r_lo * EMBED + col] = L;
        split2(o[j][2] * inv_hi, o[j][3] * inv_hi, H, L);
        *(uint32_t*)&ohi[obase + (size_t)(r_lo + 8) * EMBED + col] = H;
        *(uint32_t*)&olo[obase + (size_t)(r_lo + 8) * EMBED + col] = L;
    }
}

// ---------------------------------------------------------------------------
typedef CUresult (CUDAAPI *tmap_fn_t)(CUtensorMap*, CUtensorMapDataType, cuuint32_t,
    void*, const cuuint64_t*, const cuuint64_t*, const cuuint32_t*, const cuuint32_t*,
    CUtensorMapInterleave, CUtensorMapSwizzle, CUtensorMapL2promotion, CUtensorMapFloatOOBfill);

static void make_map(CUtensorMap* m, tmap_fn_t fn, void* base,
                     uint64_t cols, uint64_t rows)
{
    cuuint64_t dims[2]    = { cols, rows };
    cuuint64_t strides[1] = { cols * 2 };
    cuuint32_t box[2]     = { 64, 128 };
    cuuint32_t es[2]      = { 1, 1 };
    fn(m, CU_TENSOR_MAP_DATA_TYPE_BFLOAT16, 2, base, dims, strides, box, es,
       CU_TENSOR_MAP_INTERLEAVE_NONE, CU_TENSOR_MAP_SWIZZLE_128B,
       CU_TENSOR_MAP_L2_PROMOTION_L2_128B, CU_TENSOR_MAP_FLOAT_OOB_FILL_NONE);
}

extern "C" void kernel_launch(void* const* d_in, const int* in_sizes, int n_in,
                              void* d_out, int out_size)
{
    const float* x      = (const float*)d_in[0];
    const float* w_qkv  = (const float*)d_in[1];
    const float* b_qkv  = (const float*)d_in[2];
    const float* w_proj = (const float*)d_in[3];
    const float* b_proj = (const float*)d_in[4];
    float* out = (float*)d_out;

    __nv_bfloat16 *xhi, *xlo, *wqh, *wql, *wph, *wpl, *qh, *ql, *ahi, *alo;
    cudaGetSymbolAddress((void**)&xhi, g_xhi);
    cudaGetSymbolAddress((void**)&xlo, g_xlo);
    cudaGetSymbolAddress((void**)&wqh, g_wqh);
    cudaGetSymbolAddress((void**)&wql, g_wql);
    cudaGetSymbolAddress((void**)&wph, g_wph);
    cudaGetSymbolAddress((void**)&wpl, g_wpl);
    cudaGetSymbolAddress((void**)&qh, g_qh);
    cudaGetSymbolAddress((void**)&ql, g_ql);
    cudaGetSymbolAddress((void**)&ahi, g_ahi);
    cudaGetSymbolAddress((void**)&alo, g_alo);

    tmap_fn_t fn = nullptr;
    cudaDriverEntryPointQueryResult qres;
    cudaGetDriverEntryPoint("cuTensorMapEncodeTiled", (void**)&fn,
                            cudaEnableDefault, &qres);

    static CUtensorMap mXh, mXl, mWqh, mWql, mWph, mWpl, mQh, mQl, mAh, mAl;
    make_map(&mXh,  fn, xhi, EMBED,     MTOT);
    make_map(&mXl,  fn, xlo, EMBED,     MTOT);
    make_map(&mWqh, fn, wqh, EMBED,     3 * EMBED);
    make_map(&mWql, fn, wql, EMBED,     3 * EMBED);
    make_map(&mWph, fn, wph, EMBED,     EMBED);
    make_map(&mWpl, fn, wpl, EMBED,     EMBED);
    make_map(&mQh,  fn, qh,  3 * EMBED, MTOT);
    make_map(&mQl,  fn, ql,  3 * EMBED, MTOT);
    make_map(&mAh,  fn, ahi, EMBED,     MTOT);
    make_map(&mAl,  fn, alo, EMBED,     MTOT);

    const int M = MTOT;
    cudaFuncSetAttribute(gemm_tma<0>, cudaFuncAttributeMaxDynamicSharedMemorySize, GSM);
    cudaFuncSetAttribute(gemm_tma<1>, cudaFuncAttributeMaxDynamicSharedMemorySize, GSM);
    cudaFuncSetAttribute(attn_tma,    cudaFuncAttributeMaxDynamicSharedMemorySize, ASM_BYTES);

    // fused splits (x, w_qkv, w_proj in one launch)
    {
        const int total = N4_X + N4_WQ + N4_WP;
        split3_kernel<<<(total + 255) / 256, 256>>>(x, xhi, xlo,
                                                    w_qkv, wqh, wql,
                                                    w_proj, wph, wpl);
    }

    // 1) QKV projection -> bf16 hi/lo (Q pre-scaled by 0.125)
    {
        dim3 g(3 * EMBED / 128, M / 128);
        gemm_tma<1><<<g, 512, GSM>>>(mXh, mXl, mWqh, mWql, b_qkv,
                                     nullptr, qh, ql, M, 3 * EMBED, EMBED);
    }

    // 2) attention (TMA + tensor cores) -> bf16 hi/lo
    {
        dim3 g(SEQ / 128, HEADS, BATCH);
        attn_tma<<<g, 256, ASM_BYTES>>>(mQh, mQl, ahi, alo);
    }

    // 3) proj GEMM -> fp32 out
    {
        dim3 g(EMBED / 128, M / 128);
        gemm_tma<0><<<g, 512, GSM>>>(mAh, mAl, mWph, mWpl, b_proj,
                                     out, nullptr, nullptr, M, EMBED, EMBED);
    }
}

// round 10
// speedup vs baseline: 1.1243x; 1.1243x over previous
#include <cuda_runtime.h>
#include <cuda.h>
#include <cuda_bf16.h>
#include <cuda_fp16.h>
#include <cstdint>

#define EMBED    1024
#define HEADS    16
#define HEAD_DIM 64
#define SEQ      2048
#define BATCH    2
#define MTOT     (BATCH * SEQ)    // 4096

// ------------------------------ scratch (TMA needs alignment) ---------------
__device__ __align__(1024) __nv_bfloat16 g_xhi[(size_t)MTOT * EMBED];
__device__ __align__(1024) __nv_bfloat16 g_xlo[(size_t)MTOT * EMBED];
__device__ __align__(1024) __nv_bfloat16 g_wqh[(size_t)3 * EMBED * EMBED];
__device__ __align__(1024) __nv_bfloat16 g_wql[(size_t)3 * EMBED * EMBED];
__device__ __align__(1024) __nv_bfloat16 g_wph[(size_t)EMBED * EMBED];
__device__ __align__(1024) __nv_bfloat16 g_wpl[(size_t)EMBED * EMBED];
__device__ __align__(1024) __nv_bfloat16 g_qh[(size_t)MTOT * 3 * EMBED];  // fp16 bits
__device__ __align__(1024) __nv_bfloat16 g_ql[(size_t)MTOT * 3 * EMBED];  // fp16 bits
__device__ __align__(1024) __nv_bfloat16 g_ahi[(size_t)MTOT * EMBED];
__device__ __align__(1024) __nv_bfloat16 g_alo[(size_t)MTOT * EMBED];

// --------------------------- PTX helpers ------------------------------------
__device__ __forceinline__ uint32_t smem_u32(const void* p) {
    uint32_t a;
    asm("{ .reg .u64 t; cvta.to.shared.u64 t, %1; cvt.u32.u64 %0, t; }" : "=r"(a) : "l"(p));
    return a;
}
__device__ __forceinline__ void ldsm4(uint32_t* a, uint32_t addr) {
    asm volatile("ldmatrix.sync.aligned.m8n8.x4.shared.b16 {%0,%1,%2,%3}, [%4];"
                 : "=r"(a[0]), "=r"(a[1]), "=r"(a[2]), "=r"(a[3]) : "r"(addr));
}
__device__ __forceinline__ void ldsm2(uint32_t* b, uint32_t addr) {
    asm volatile("ldmatrix.sync.aligned.m8n8.x2.shared.b16 {%0,%1}, [%2];"
                 : "=r"(b[0]), "=r"(b[1]) : "r"(addr));
}
__device__ __forceinline__ void ldsm2t(uint32_t* b, uint32_t addr) {
    asm volatile("ldmatrix.sync.aligned.m8n8.x2.trans.shared.b16 {%0,%1}, [%2];"
                 : "=r"(b[0]), "=r"(b[1]) : "r"(addr));
}
__device__ __forceinline__ void mma16816(float* c, const uint32_t* a, const uint32_t* b) {
    asm volatile(
        "mma.sync.aligned.m16n8k16.row.col.f32.bf16.bf16.f32 "
        "{%0,%1,%2,%3},{%4,%5,%6,%7},{%8,%9},{%0,%1,%2,%3};"
        : "+f"(c[0]), "+f"(c[1]), "+f"(c[2]), "+f"(c[3])
        : "r"(a[0]), "r"(a[1]), "r"(a[2]), "r"(a[3]), "r"(b[0]), "r"(b[1]));
}
__device__ __forceinline__ void mma16816h(float* c, const uint32_t* a, const uint32_t* b) {
    asm volatile(
        "mma.sync.aligned.m16n8k16.row.col.f32.f16.f16.f32 "
        "{%0,%1,%2,%3},{%4,%5,%6,%7},{%8,%9},{%0,%1,%2,%3};"
        : "+f"(c[0]), "+f"(c[1]), "+f"(c[2]), "+f"(c[3])
        : "r"(a[0]), "r"(a[1]), "r"(a[2]), "r"(a[3]), "r"(b[0]), "r"(b[1]));
}
__device__ __forceinline__ void tma2d(uint32_t s, const CUtensorMap* m, int x, int y, uint32_t mb) {
    asm volatile(
        "cp.async.bulk.tensor.2d.shared::cta.global.tile.mbarrier::complete_tx::bytes "
        "[%0], [%1, {%2, %3}], [%4];"
        :: "r"(s), "l"(m), "r"(x), "r"(y), "r"(mb) : "memory");
}
__device__ __forceinline__ void mb_init(uint32_t mb, uint32_t cnt) {
    asm volatile("mbarrier.init.shared.b64 [%0], %1;" :: "r"(mb), "r"(cnt) : "memory");
}
__device__ __forceinline__ void mb_expect(uint32_t mb, uint32_t bytes) {
    asm volatile("mbarrier.arrive.expect_tx.shared.b64 _, [%0], %1;" :: "r"(mb), "r"(bytes) : "memory");
}
#define MBWAIT(mb, ph)                                                          \
    asm volatile("{\n .reg .pred p;\nWL%=:\n"                                   \
                 " mbarrier.try_wait.parity.shared.b64 p, [%0], %1;\n"          \
                 " @!p bra WL%=;\n}"                                            \
                 :: "r"(mb), "r"((uint32_t)(ph)) : "memory")

__device__ __forceinline__ uint32_t pack2(float a, float b) {
    __nv_bfloat162 t = __floats2bfloat162_rn(a, b);
    return *(uint32_t*)&t;
}
__device__ __forceinline__ void split2(float a, float b, uint32_t& H, uint32_t& L) {
    __nv_bfloat16 ha = __float2bfloat16(a), hb = __float2bfloat16(b);
    float la = a - __bfloat162float(ha), lb = b - __bfloat162float(hb);
    H = ((uint32_t)__bfloat16_as_ushort(hb) << 16) | __bfloat16_as_ushort(ha);
    L = pack2(la, lb);
}
// fp16 split: hi = fp16(x), lo = fp16(x - hi)
__device__ __forceinline__ void split2h(float a, float b, uint32_t& H, uint32_t& L) {
    __half ha = __float2half_rn(a), hb = __float2half_rn(b);
    float la = a - __half2float(ha), lb = b - __half2float(hb);
    __half hla = __float2half_rn(la), hlb = __float2half_rn(lb);
    H = ((uint32_t)__half_as_ushort(hb) << 16) | __half_as_ushort(ha);
    L = ((uint32_t)__half_as_ushort(hlb) << 16) | __half_as_ushort(hla);
}

// -------------- fp32 -> (bf16 hi, bf16 lo), 3 tensors in one launch ---------
#define N4_X  (MTOT * EMBED / 4)
#define N4_WQ (3 * EMBED * EMBED / 4)
#define N4_WP (EMBED * EMBED / 4)

__global__ __launch_bounds__(256)
void split3_kernel(const float* __restrict__ x,  __nv_bfloat16* __restrict__ xh, __nv_bfloat16* __restrict__ xl,
                   const float* __restrict__ wq, __nv_bfloat16* __restrict__ qh, __nv_bfloat16* __restrict__ ql,
                   const float* __restrict__ wp, __nv_bfloat16* __restrict__ ph, __nv_bfloat16* __restrict__ pl)
{
    int i = blockIdx.x * blockDim.x + threadIdx.x;
    const float* in; __nv_bfloat16 *hi, *lo;
    if (i < N4_X)                { in = x;  hi = xh; lo = xl; }
    else if (i < N4_X + N4_WQ)   { in = wq; hi = qh; lo = ql; i -= N4_X; }
    else if (i < N4_X + N4_WQ + N4_WP) { in = wp; hi = ph; lo = pl; i -= N4_X + N4_WQ; }
    else return;
    float4 v = ((const float4*)in)[i];
    uint2 H, L;
    split2(v.x, v.y, H.x, L.x);
    split2(v.z, v.w, H.y, L.y);
    ((uint2*)hi)[i] = H;
    ((uint2*)lo)[i] = L;
}

// ----------- TMA + mma.sync bf16x3 GEMM: C = A W^T + bias -------------------
// MODE 0: fp32 out. MODE 1: fp16 hi/lo out, cols < 1024 scaled by 0.125 (Q).
#define GSTG 65536
#define GSM  (1024 + 3 * GSTG)

template<int MODE>
__global__ __launch_bounds__(512)
void gemm_tma(const __grid_constant__ CUtensorMap mAh,
              const __grid_constant__ CUtensorMap mAl,
              const __grid_constant__ CUtensorMap mBh,
              const __grid_constant__ CUtensorMap mBl,
              const float* __restrict__ bias, float* __restrict__ C,
              __nv_bfloat16* __restrict__ Chi, __nv_bfloat16* __restrict__ Clo,
              int M, int N, int K)
{
    extern __shared__ char smem[];
    __shared__ uint64_t mbar[3];
    const uint32_t sb0 = (smem_u32(smem) + 1023) & ~1023u;

    const int t = threadIdx.x, lane = t & 31, wid = t >> 5;
    const int row0 = blockIdx.y * 128, col0 = blockIdx.x * 128;
    const int m0 = (wid >> 2) * 32, n0 = (wid & 3) * 32;

    uint32_t mb[3];
    #pragma unroll
    for (int s = 0; s < 3; s++) mb[s] = smem_u32(&mbar[s]);
    if (t == 0) {
        #pragma unroll
        for (int s = 0; s < 3; s++) mb_init(mb[s], 1);
    }
    __syncthreads();

    auto issue = [&](int kt) {
        const int s = kt % 3;
        const uint32_t base = sb0 + s * GSTG;
        mb_expect(mb[s], GSTG);
        tma2d(base,         &mAh, kt * 64, row0, mb[s]);
        tma2d(base + 16384, &mAl, kt * 64, row0, mb[s]);
        tma2d(base + 32768, &mBh, kt * 64, col0, mb[s]);
        tma2d(base + 49152, &mBl, kt * 64, col0, mb[s]);
    };
    if (t == 0) { issue(0); issue(1); }

    float c[2][4][4] = {};
    const int KT = K / 64;

    for (int kt = 0; kt < KT; kt++) {
        if (t == 0 && kt + 2 < KT) issue(kt + 2);
        const int s = kt % 3;
        MBWAIT(mb[s], (kt / 3) & 1);
        const uint32_t base = sb0 + s * GSTG;
        const uint32_t aAh = base, aAl = base + 16384, aBh = base + 32768, aBl = base + 49152;

        #pragma unroll
        for (int ks = 0; ks < 4; ks++) {
            uint32_t ad[2], bd[4];
            #pragma unroll
            for (int i = 0; i < 2; i++) {
                const int r = m0 + (lane & 15) + i * 16;
                const int ch = 2 * ks + (lane >> 4);
                ad[i] = (uint32_t)(r * 128 + ((ch ^ (r & 7)) << 4));
            }
            #pragma unroll
            for (int j = 0; j < 4; j++) {
                const int r = n0 + (lane & 7) + j * 8;
                const int ch = 2 * ks + ((lane >> 3) & 1);
                bd[j] = (uint32_t)(r * 128 + ((ch ^ (r & 7)) << 4));
            }
            uint32_t ah[2][4], al[2][4], bh[4][2], bl[4][2];
            #pragma unroll
            for (int i = 0; i < 2; i++) ldsm4(ah[i], aAh + ad[i]);
            #pragma unroll
            for (int j = 0; j < 4; j++) ldsm2(bh[j], aBh + bd[j]);
            #pragma unroll
            for (int i = 0; i < 2; i++)
                #pragma unroll
                for (int j = 0; j < 4; j++) mma16816(c[i][j], ah[i], bh[j]);
            #pragma unroll
            for (int j = 0; j < 4; j++) ldsm2(bl[j], aBl + bd[j]);
            #pragma unroll
            for (int i = 0; i < 2; i++)
                #pragma unroll
                for (int j = 0; j < 4; j++) mma16816(c[i][j], ah[i], bl[j]);
            #pragma unroll
            for (int i = 0; i < 2; i++) ldsm4(al[i], aAl + ad[i]);
            #pragma unroll
            for (int i = 0; i < 2; i++)
                #pragma unroll
                for (int j = 0; j < 4; j++) mma16816(c[i][j], al[i], bh[j]);
        }
        __syncthreads();
    }

    #pragma unroll
    for (int j = 0; j < 4; j++) {
        const int col = col0 + n0 + j * 8 + (lane & 3) * 2;
        const float2 bb = *(const float2*)&bias[col];
        const float sc = (MODE == 1 && col < EMBED) ? 0.125f : 1.0f;
        #pragma unroll
        for (int i = 0; i < 2; i++) {
            const int r0 = row0 + m0 + i * 16 + (lane >> 2);
            float v0 = (c[i][j][0] + bb.x) * sc, v1 = (c[i][j][1] + bb.y) * sc;
            float v2 = (c[i][j][2] + bb.x) * sc, v3 = (c[i][j][3] + bb.y) * sc;
            if (MODE == 0) {
                *(float2*)&C[(size_t)r0 * N + col]       = make_float2(v0, v1);
                *(float2*)&C[(size_t)(r0 + 8) * N + col] = make_float2(v2, v3);
            } else {
                uint32_t H, L;
                split2h(v0, v1, H, L);
                *(uint32_t*)&Chi[(size_t)r0 * N + col] = H;
                *(uint32_t*)&Clo[(size_t)r0 * N + col] = L;
                split2h(v2, v3, H, L);
                *(uint32_t*)&Chi[(size_t)(r0 + 8) * N + col] = H;
                *(uint32_t*)&Clo[(size_t)(r0 + 8) * N + col] = L;
            }
        }
    }
}

// -------------- TMA + fp16 2-mma flash attention -----------------------------
// Q: fp16 hi+lo (exact). K, V: single fp16 (hi only).
// S = Qh*K + Ql*K ; O = Ph*V + Pl*V (P split in-register).
#define ASTG2 32768                           // Kh + Vh per stage
#define ASM_BYTES (1024 + 2 * 16384 + 3 * ASTG2)

__global__ __launch_bounds__(256)
void attn_tma(const __grid_constant__ CUtensorMap mQh,
              const __grid_constant__ CUtensorMap mQl,
              __nv_bfloat16* __restrict__ ohi, __nv_bfloat16* __restrict__ olo)
{
    extern __shared__ char smem[];
    __shared__ uint64_t mbar[4];   // [0]=Q, [1..3]=KV stages
    const uint32_t sb0 = (smem_u32(smem) + 1023) & ~1023u;
    const uint32_t sQh = sb0, sQl = sb0 + 16384;
    const uint32_t sKV = sb0 + 32768;

    const int t = threadIdx.x, lane = t & 31, wid = t >> 5;
    const int qt = blockIdx.x, h = blockIdx.y, b = blockIdx.z;
    const int qrow = b * SEQ + qt * 128;

    uint32_t qb = smem_u32(&mbar[0]);
    uint32_t kb[3] = { smem_u32(&mbar[1]), smem_u32(&mbar[2]), smem_u32(&mbar[3]) };
    if (t == 0) { mb_init(qb, 1); mb_init(kb[0], 1); mb_init(kb[1], 1); mb_init(kb[2], 1); }
    __syncthreads();

    auto issueKV = [&](int kt) {
        const int s = kt % 3;
        const uint32_t base = sKV + s * ASTG2;
        const int krow = b * SEQ + kt * 128;
        mb_expect(kb[s], ASTG2);
        tma2d(base,         &mQh, EMBED + h * HEAD_DIM,     krow, kb[s]);   // K (fp16 hi)
        tma2d(base + 16384, &mQh, 2 * EMBED + h * HEAD_DIM, krow, kb[s]);   // V (fp16 hi)
    };
    if (t == 0) {
        mb_expect(qb, 32768);
        tma2d(sQh, &mQh, h * HEAD_DIM, qrow, qb);
        tma2d(sQl, &mQl, h * HEAD_DIM, qrow, qb);
        issueKV(0); issueKV(1); issueKV(2);
    }

    uint32_t qfh[4][4], qfl[4][4];
    MBWAIT(qb, 0);
    #pragma unroll
    for (int ks = 0; ks < 4; ks++) {
        const int r = wid * 16 + (lane & 15);
        const int ch = 2 * ks + (lane >> 4);
        const uint32_t qd = (uint32_t)(r * 128 + ((ch ^ (r & 7)) << 4));
        ldsm4(qfh[ks], sQh + qd);
        ldsm4(qfl[ks], sQl + qd);
    }

    float o[8][4] = {};
    float m_lo = -1e30f, m_hi = -1e30f, l_lo = 0.0f, l_hi = 0.0f;

    const int NKV = SEQ / 128;
    for (int kt = 0; kt < NKV; kt++) {
        const int s = kt % 3;
        MBWAIT(kb[s], (kt / 3) & 1);
        const uint32_t base = sKV + s * ASTG2;
        const uint32_t aKh = base, aVh = base + 16384;

        // ---- S = Qh*K + Ql*K ----
        float sfr[16][4] = {};
        #pragma unroll
        for (int ks = 0; ks < 4; ks++) {
            uint32_t kd[16];
            #pragma unroll
            for (int j = 0; j < 16; j++) {
                const int r = j * 8 + (lane & 7);
                const int ch = 2 * ks + ((lane >> 3) & 1);
                kd[j] = (uint32_t)(r * 128 + ((ch ^ (r & 7)) << 4));
            }
            uint32_t kf[16][2];
            #pragma unroll
            for (int j = 0; j < 16; j++) ldsm2(kf[j], aKh + kd[j]);
            #pragma unroll
            for (int j = 0; j < 16; j++) mma16816h(sfr[j], qfh[ks], kf[j]);
            #pragma unroll
            for (int j = 0; j < 16; j++) mma16816h(sfr[j], qfl[ks], kf[j]);
        }

        // ---- online softmax ----
        float tmax_lo = -1e30f, tmax_hi = -1e30f;
        #pragma unroll
        for (int j = 0; j < 16; j++) {
            tmax_lo = fmaxf(tmax_lo, fmaxf(sfr[j][0], sfr[j][1]));
            tmax_hi = fmaxf(tmax_hi, fmaxf(sfr[j][2], sfr[j][3]));
        }
        tmax_lo = fmaxf(tmax_lo, __shfl_xor_sync(0xffffffffu, tmax_lo, 1));
        tmax_lo = fmaxf(tmax_lo, __shfl_xor_sync(0xffffffffu, tmax_lo, 2));
        tmax_hi = fmaxf(tmax_hi, __shfl_xor_sync(0xffffffffu, tmax_hi, 1));
        tmax_hi = fmaxf(tmax_hi, __shfl_xor_sync(0xffffffffu, tmax_hi, 2));
        float mn_lo = fmaxf(m_lo, tmax_lo), mn_hi = fmaxf(m_hi, tmax_hi);
        float corr_lo = __expf(m_lo - mn_lo), corr_hi = __expf(m_hi - mn_hi);
        m_lo = mn_lo; m_hi = mn_hi;

        float sum_lo = 0.0f, sum_hi = 0.0f;
        #pragma unroll
        for (int j = 0; j < 16; j++) {
            sfr[j][0] = __expf(sfr[j][0] - m_lo); sfr[j][1] = __expf(sfr[j][1] - m_lo);
            sfr[j][2] = __expf(sfr[j][2] - m_hi); sfr[j][3] = __expf(sfr[j][3] - m_hi);
            sum_lo += sfr[j][0] + sfr[j][1];
            sum_hi += sfr[j][2] + sfr[j][3];
        }
        sum_lo += __shfl_xor_sync(0xffffffffu, sum_lo, 1);
        sum_lo += __shfl_xor_sync(0xffffffffu, sum_lo, 2);
        sum_hi += __shfl_xor_sync(0xffffffffu, sum_hi, 1);
        sum_hi += __shfl_xor_sync(0xffffffffu, sum_hi, 2);
        l_lo = l_lo * corr_lo + sum_lo;
        l_hi = l_hi * corr_hi + sum_hi;
        #pragma unroll
        for (int j = 0; j < 8; j++) {
            o[j][0] *= corr_lo; o[j][1] *= corr_lo;
            o[j][2] *= corr_hi; o[j][3] *= corr_hi;
        }

        // ---- O += Ph*V + Pl*V ----
        #pragma unroll
        for (int kk = 0; kk < 8; kk++) {
            uint32_t ph[4], pl[4];
            split2h(sfr[2*kk  ][0], sfr[2*kk  ][1], ph[0], pl[0]);
            split2h(sfr[2*kk  ][2], sfr[2*kk  ][3], ph[1], pl[1]);
            split2h(sfr[2*kk+1][0], sfr[2*kk+1][1], ph[2], pl[2]);
            split2h(sfr[2*kk+1][2], sfr[2*kk+1][3], ph[3], pl[3]);

            const int r = kk * 16 + (lane & 15);
            uint32_t vf[8][2];
            #pragma unroll
            for (int j = 0; j < 8; j++)
                ldsm2t(vf[j], aVh + (uint32_t)(r * 128 + ((j ^ (r & 7)) << 4)));
            #pragma unroll
            for (int j = 0; j < 8; j++) mma16816h(o[j], ph, vf[j]);
            #pragma unroll
            for (int j = 0; j < 8; j++) mma16816h(o[j], pl, vf[j]);
        }
        __syncthreads();
        if (t == 0 && kt + 3 < NKV) issueKV(kt + 3);
    }

    // ---- epilogue: normalize + bf16 hi/lo out (proj GEMM input) ----
    const float inv_lo = 1.0f / l_lo, inv_hi = 1.0f / l_hi;
    const int r_lo = qt * 128 + wid * 16 + (lane >> 2);
    const size_t obase = (size_t)(b * SEQ) * EMBED + (size_t)h * HEAD_DIM;
    #pragma unroll
    for (int j = 0; j < 8; j++) {
        const int col = j * 8 + (lane & 3) * 2;
        uint32_t H, L;
        split2(o[j][0] * inv_lo, o[j][1] * inv_lo, H, L);
        *(uint32_t*)&ohi[obase + (size_t)r_lo * EMBED + col] = H;
        *(uint32_t*)&olo[obase + (size_t)r_lo * EMBED + col] = L;
        split2(o[j][2] * inv_hi, o[j][3] * inv_hi, H, L);
        *(uint32_t*)&ohi[obase + (size_t)(r_lo + 8) * EMBED + col] = H;
        *(uint32_t*)&olo[obase + (size_t)(r_lo + 8) * EMBED + col] = L;
    }
}

// ---------------------------------------------------------------------------
typedef CUresult (CUDAAPI *tmap_fn_t)(CUtensorMap*, CUtensorMapDataType, cuuint32_t,
    void*, const cuuint64_t*, const cuuint64_t*, const cuuint32_t*, const cuuint32_t*,
    CUtensorMapInterleave, CUtensorMapSwizzle, CUtensorMapL2promotion, CUtensorMapFloatOOBfill);

static void make_map(CUtensorMap* m, tmap_fn_t fn, void* base,
                     uint64_t cols, uint64_t rows)
{
    cuuint64_t dims[2]    = { cols, rows };
    cuuint64_t strides[1] = { cols * 2 };
    cuuint32_t box[2]     = { 64, 128 };
    cuuint32_t es[2]      = { 1, 1 };
    fn(m, CU_TENSOR_MAP_DATA_TYPE_BFLOAT16, 2, base, dims, strides, box, es,
       CU_TENSOR_MAP_INTERLEAVE_NONE, CU_TENSOR_MAP_SWIZZLE_128B,
       CU_TENSOR_MAP_L2_PROMOTION_L2_128B, CU_TENSOR_MAP_FLOAT_OOB_FILL_NONE);
}

extern "C" void kernel_launch(void* const* d_in, const int* in_sizes, int n_in,
                              void* d_out, int out_size)
{
    const float* x      = (const float*)d_in[0];
    const float* w_qkv  = (const float*)d_in[1];
    const float* b_qkv  = (const float*)d_in[2];
    const float* w_proj = (const float*)d_in[3];
    const float* b_proj = (const float*)d_in[4];
    float* out = (float*)d_out;

    __nv_bfloat16 *xhi, *xlo, *wqh, *wql, *wph, *wpl, *qh, *ql, *ahi, *alo;
    cudaGetSymbolAddress((void**)&xhi, g_xhi);
    cudaGetSymbolAddress((void**)&xlo, g_xlo);
    cudaGetSymbolAddress((void**)&wqh, g_wqh);
    cudaGetSymbolAddress((void**)&wql, g_wql);
    cudaGetSymbolAddress((void**)&wph, g_wph);
    cudaGetSymbolAddress((void**)&wpl, g_wpl);
    cudaGetSymbolAddress((void**)&qh, g_qh);
    cudaGetSymbolAddress((void**)&ql, g_ql);
    cudaGetSymbolAddress((void**)&ahi, g_ahi);
    cudaGetSymbolAddress((void**)&alo, g_alo);

    tmap_fn_t fn = nullptr;
    cudaDriverEntryPointQueryResult qres;
    cudaGetDriverEntryPoint("cuTensorMapEncodeTiled", (void**)&fn,
                            cudaEnableDefault, &qres);

    static CUtensorMap mXh, mXl, mWqh, mWql, mWph, mWpl, mQh, mQl, mAh, mAl;
    make_map(&mXh,  fn, xhi, EMBED,     MTOT);
    make_map(&mXl,  fn, xlo, EMBED,     MTOT);
    make_map(&mWqh, fn, wqh, EMBED,     3 * EMBED);
    make_map(&mWql, fn, wql, EMBED,     3 * EMBED);
    make_map(&mWph, fn, wph, EMBED,     EMBED);
    make_map(&mWpl, fn, wpl, EMBED,     EMBED);
    make_map(&mQh,  fn, qh,  3 * EMBED, MTOT);
    make_map(&mQl,  fn, ql,  3 * EMBED, MTOT);
    make_map(&mAh,  fn, ahi, EMBED,     MTOT);
    make_map(&mAl,  fn, alo, EMBED,     MTOT);

    const int M = MTOT;
    cudaFuncSetAttribute(gemm_tma<0>, cudaFuncAttributeMaxDynamicSharedMemorySize, GSM);
    cudaFuncSetAttribute(gemm_tma<1>, cudaFuncAttributeMaxDynamicSharedMemorySize, GSM);
    cudaFuncSetAttribute(attn_tma,    cudaFuncAttributeMaxDynamicSharedMemorySize, ASM_BYTES);

    // fused splits (x, w_qkv, w_proj in one launch)
    {
        const int total = N4_X + N4_WQ + N4_WP;
        split3_kernel<<<(total + 255) / 256, 256>>>(x, xhi, xlo,
                                                    w_qkv, wqh, wql,
                                                    w_proj, wph, wpl);
    }

    // 1) QKV projection -> fp16 hi/lo (Q pre-scaled by 0.125)
    {
        dim3 g(3 * EMBED / 128, M / 128);
        gemm_tma<1><<<g, 512, GSM>>>(mXh, mXl, mWqh, mWql, b_qkv,
                                     nullptr, qh, ql, M, 3 * EMBED, EMBED);
    }

    // 2) attention (fp16 2-mma scheme) -> bf16 hi/lo
    {
        dim3 g(SEQ / 128, HEADS, BATCH);
        attn_tma<<<g, 256, ASM_BYTES>>>(mQh, mQl, ahi, alo);
    }

    // 3) proj GEMM -> fp32 out
    {
        dim3 g(EMBED / 128, M / 128);
        gemm_tma<0><<<g, 512, GSM>>>(mAh, mAl, mWph, mWpl, b_proj,
                                     out, nullptr, nullptr, M, EMBED, EMBED);
    }
}

// round 11
// speedup vs baseline: 1.3218x; 1.1757x over previous
#include <cuda_runtime.h>
#include <cuda.h>
#include <cuda_bf16.h>
#include <cuda_fp16.h>
#include <cstdint>

#define EMBED    1024
#define HEADS    16
#define HEAD_DIM 64
#define SEQ      2048
#define BATCH    2
#define MTOT     (BATCH * SEQ)    // 4096

// ------------------------------ scratch (TMA needs alignment) ---------------
// All 16-bit buffers hold fp16 bit patterns (declared bf16 for storage only).
__device__ __align__(1024) __nv_bfloat16 g_xhi[(size_t)MTOT * EMBED];
__device__ __align__(1024) __nv_bfloat16 g_xlo[(size_t)MTOT * EMBED];
__device__ __align__(1024) __nv_bfloat16 g_wqh[(size_t)3 * EMBED * EMBED];
__device__ __align__(1024) __nv_bfloat16 g_wph[(size_t)EMBED * EMBED];
__device__ __align__(1024) __nv_bfloat16 g_qh[(size_t)MTOT * 3 * EMBED];
__device__ __align__(1024) __nv_bfloat16 g_ql[(size_t)MTOT * 3 * EMBED];
__device__ __align__(1024) __nv_bfloat16 g_ahi[(size_t)MTOT * EMBED];
__device__ __align__(1024) __nv_bfloat16 g_alo[(size_t)MTOT * EMBED];

// --------------------------- PTX helpers ------------------------------------
__device__ __forceinline__ uint32_t smem_u32(const void* p) {
    uint32_t a;
    asm("{ .reg .u64 t; cvta.to.shared.u64 t, %1; cvt.u32.u64 %0, t; }" : "=r"(a) : "l"(p));
    return a;
}
__device__ __forceinline__ void ldsm4(uint32_t* a, uint32_t addr) {
    asm volatile("ldmatrix.sync.aligned.m8n8.x4.shared.b16 {%0,%1,%2,%3}, [%4];"
                 : "=r"(a[0]), "=r"(a[1]), "=r"(a[2]), "=r"(a[3]) : "r"(addr));
}
__device__ __forceinline__ void ldsm2(uint32_t* b, uint32_t addr) {
    asm volatile("ldmatrix.sync.aligned.m8n8.x2.shared.b16 {%0,%1}, [%2];"
                 : "=r"(b[0]), "=r"(b[1]) : "r"(addr));
}
__device__ __forceinline__ void ldsm2t(uint32_t* b, uint32_t addr) {
    asm volatile("ldmatrix.sync.aligned.m8n8.x2.trans.shared.b16 {%0,%1}, [%2];"
                 : "=r"(b[0]), "=r"(b[1]) : "r"(addr));
}
__device__ __forceinline__ void mma16816h(float* c, const uint32_t* a, const uint32_t* b) {
    asm volatile(
        "mma.sync.aligned.m16n8k16.row.col.f32.f16.f16.f32 "
        "{%0,%1,%2,%3},{%4,%5,%6,%7},{%8,%9},{%0,%1,%2,%3};"
        : "+f"(c[0]), "+f"(c[1]), "+f"(c[2]), "+f"(c[3])
        : "r"(a[0]), "r"(a[1]), "r"(a[2]), "r"(a[3]), "r"(b[0]), "r"(b[1]));
}
__device__ __forceinline__ void tma2d(uint32_t s, const CUtensorMap* m, int x, int y, uint32_t mb) {
    asm volatile(
        "cp.async.bulk.tensor.2d.shared::cta.global.tile.mbarrier::complete_tx::bytes "
        "[%0], [%1, {%2, %3}], [%4];"
        :: "r"(s), "l"(m), "r"(x), "r"(y), "r"(mb) : "memory");
}
__device__ __forceinline__ void mb_init(uint32_t mb, uint32_t cnt) {
    asm volatile("mbarrier.init.shared.b64 [%0], %1;" :: "r"(mb), "r"(cnt) : "memory");
}
__device__ __forceinline__ void mb_expect(uint32_t mb, uint32_t bytes) {
    asm volatile("mbarrier.arrive.expect_tx.shared.b64 _, [%0], %1;" :: "r"(mb), "r"(bytes) : "memory");
}
#define MBWAIT(mb, ph)                                                          \
    asm volatile("{\n .reg .pred p;\nWL%=:\n"                                   \
                 " mbarrier.try_wait.parity.shared.b64 p, [%0], %1;\n"          \
                 " @!p bra WL%=;\n}"                                            \
                 :: "r"(mb), "r"((uint32_t)(ph)) : "memory")

// fp16 helpers
__device__ __forceinline__ uint32_t pack2h(float a, float b) {
    __half ha = __float2half_rn(a), hb = __float2half_rn(b);
    return ((uint32_t)__half_as_ushort(hb) << 16) | __half_as_ushort(ha);
}
__device__ __forceinline__ void split2h(float a, float b, uint32_t& H, uint32_t& L) {
    __half ha = __float2half_rn(a), hb = __float2half_rn(b);
    float la = a - __half2float(ha), lb = b - __half2float(hb);
    H = ((uint32_t)__half_as_ushort(hb) << 16) | __half_as_ushort(ha);
    L = pack2h(la, lb);
}

// ---- fp32 -> fp16: x as hi/lo pair; w_qkv, w_proj as single fp16 ------------
#define N4_X  (MTOT * EMBED / 4)
#define N4_WQ (3 * EMBED * EMBED / 4)
#define N4_WP (EMBED * EMBED / 4)

__global__ __launch_bounds__(256)
void split3_kernel(const float* __restrict__ x,  __nv_bfloat16* __restrict__ xh, __nv_bfloat16* __restrict__ xl,
                   const float* __restrict__ wq, __nv_bfloat16* __restrict__ wqh,
                   const float* __restrict__ wp, __nv_bfloat16* __restrict__ wph)
{
    int i = blockIdx.x * blockDim.x + threadIdx.x;
    if (i < N4_X) {
        float4 v = ((const float4*)x)[i];
        uint2 H, L;
        split2h(v.x, v.y, H.x, L.x);
        split2h(v.z, v.w, H.y, L.y);
        ((uint2*)xh)[i] = H;
        ((uint2*)xl)[i] = L;
        return;
    }
    const float* in; __nv_bfloat16* hi;
    if (i < N4_X + N4_WQ)                   { in = wq; hi = wqh; i -= N4_X; }
    else if (i < N4_X + N4_WQ + N4_WP)      { in = wp; hi = wph; i -= N4_X + N4_WQ; }
    else return;
    float4 v = ((const float4*)in)[i];
    uint2 H;
    H.x = pack2h(v.x, v.y);
    H.y = pack2h(v.z, v.w);
    ((uint2*)hi)[i] = H;
}

// ----------- TMA + fp16 2-term GEMM: C = A W^T + bias -----------------------
// A: fp16 hi+lo (exact). W: single fp16. C = Ah*W + Al*W.
// MODE 0: fp32 out. MODE 1: fp16 hi/lo out, cols < 1024 scaled by 0.125 (Q).
#define GSTG 49152                       // Ah + Al + B per stage (3 x 16KB)
#define GSM  (1024 + 3 * GSTG)

template<int MODE>
__global__ __launch_bounds__(512)
void gemm_tma(const __grid_constant__ CUtensorMap mAh,
              const __grid_constant__ CUtensorMap mAl,
              const __grid_constant__ CUtensorMap mB,
              const float* __restrict__ bias, float* __restrict__ C,
              __nv_bfloat16* __restrict__ Chi, __nv_bfloat16* __restrict__ Clo,
              int M, int N, int K)
{
    extern __shared__ char smem[];
    __shared__ uint64_t mbar[3];
    const uint32_t sb0 = (smem_u32(smem) + 1023) & ~1023u;

    const int t = threadIdx.x, lane = t & 31, wid = t >> 5;
    const int row0 = blockIdx.y * 128, col0 = blockIdx.x * 128;
    const int m0 = (wid >> 2) * 32, n0 = (wid & 3) * 32;

    uint32_t mb[3];
    #pragma unroll
    for (int s = 0; s < 3; s++) mb[s] = smem_u32(&mbar[s]);
    if (t == 0) {
        #pragma unroll
        for (int s = 0; s < 3; s++) mb_init(mb[s], 1);
    }
    __syncthreads();

    auto issue = [&](int kt) {
        const int s = kt % 3;
        const uint32_t base = sb0 + s * GSTG;
        mb_expect(mb[s], GSTG);
        tma2d(base,         &mAh, kt * 64, row0, mb[s]);
        tma2d(base + 16384, &mAl, kt * 64, row0, mb[s]);
        tma2d(base + 32768, &mB,  kt * 64, col0, mb[s]);
    };
    if (t == 0) { issue(0); issue(1); }

    float c[2][4][4] = {};
    const int KT = K / 64;

    for (int kt = 0; kt < KT; kt++) {
        if (t == 0 && kt + 2 < KT) issue(kt + 2);
        const int s = kt % 3;
        MBWAIT(mb[s], (kt / 3) & 1);
        const uint32_t base = sb0 + s * GSTG;
        const uint32_t aAh = base, aAl = base + 16384, aB = base + 32768;

        #pragma unroll
        for (int ks = 0; ks < 4; ks++) {
            uint32_t ad[2], bd[4];
            #pragma unroll
            for (int i = 0; i < 2; i++) {
                const int r = m0 + (lane & 15) + i * 16;
                const int ch = 2 * ks + (lane >> 4);
                ad[i] = (uint32_t)(r * 128 + ((ch ^ (r & 7)) << 4));
            }
            #pragma unroll
            for (int j = 0; j < 4; j++) {
                const int r = n0 + (lane & 7) + j * 8;
                const int ch = 2 * ks + ((lane >> 3) & 1);
                bd[j] = (uint32_t)(r * 128 + ((ch ^ (r & 7)) << 4));
            }
            uint32_t ah[2][4], al[2][4], bf[4][2];
            #pragma unroll
            for (int i = 0; i < 2; i++) ldsm4(ah[i], aAh + ad[i]);
            #pragma unroll
            for (int j = 0; j < 4; j++) ldsm2(bf[j], aB + bd[j]);
            #pragma unroll
            for (int i = 0; i < 2; i++)
                #pragma unroll
                for (int j = 0; j < 4; j++) mma16816h(c[i][j], ah[i], bf[j]);
            #pragma unroll
            for (int i = 0; i < 2; i++) ldsm4(al[i], aAl + ad[i]);
            #pragma unroll
            for (int i = 0; i < 2; i++)
                #pragma unroll
                for (int j = 0; j < 4; j++) mma16816h(c[i][j], al[i], bf[j]);
        }
        __syncthreads();
    }

    #pragma unroll
    for (int j = 0; j < 4; j++) {
        const int col = col0 + n0 + j * 8 + (lane & 3) * 2;
        const float2 bb = *(const float2*)&bias[col];
        const float sc = (MODE == 1 && col < EMBED) ? 0.125f : 1.0f;
        #pragma unroll
        for (int i = 0; i < 2; i++) {
            const int r0 = row0 + m0 + i * 16 + (lane >> 2);
            float v0 = (c[i][j][0] + bb.x) * sc, v1 = (c[i][j][1] + bb.y) * sc;
            float v2 = (c[i][j][2] + bb.x) * sc, v3 = (c[i][j][3] + bb.y) * sc;
            if (MODE == 0) {
                *(float2*)&C[(size_t)r0 * N + col]       = make_float2(v0, v1);
                *(float2*)&C[(size_t)(r0 + 8) * N + col] = make_float2(v2, v3);
            } else {
                uint32_t H, L;
                split2h(v0, v1, H, L);
                *(uint32_t*)&Chi[(size_t)r0 * N + col] = H;
                *(uint32_t*)&Clo[(size_t)r0 * N + col] = L;
                split2h(v2, v3, H, L);
                *(uint32_t*)&Chi[(size_t)(r0 + 8) * N + col] = H;
                *(uint32_t*)&Clo[(size_t)(r0 + 8) * N + col] = L;
            }
        }
    }
}

// -------------- TMA + fp16 2-mma flash attention -----------------------------
// Q: fp16 hi+lo (exact). K, V: single fp16 (hi only).
// S = Qh*K + Ql*K ; O = Ph*V + Pl*V (P split in-register).
#define ASTG2 32768                           // Kh + Vh per stage
#define ASM_BYTES (1024 + 2 * 16384 + 3 * ASTG2)

__global__ __launch_bounds__(256)
void attn_tma(const __grid_constant__ CUtensorMap mQh,
              const __grid_constant__ CUtensorMap mQl,
              __nv_bfloat16* __restrict__ ohi, __nv_bfloat16* __restrict__ olo)
{
    extern __shared__ char smem[];
    __shared__ uint64_t mbar[4];   // [0]=Q, [1..3]=KV stages
    const uint32_t sb0 = (smem_u32(smem) + 1023) & ~1023u;
    const uint32_t sQh = sb0, sQl = sb0 + 16384;
    const uint32_t sKV = sb0 + 32768;

    const int t = threadIdx.x, lane = t & 31, wid = t >> 5;
    const int qt = blockIdx.x, h = blockIdx.y, b = blockIdx.z;
    const int qrow = b * SEQ + qt * 128;

    uint32_t qb = smem_u32(&mbar[0]);
    uint32_t kb[3] = { smem_u32(&mbar[1]), smem_u32(&mbar[2]), smem_u32(&mbar[3]) };
    if (t == 0) { mb_init(qb, 1); mb_init(kb[0], 1); mb_init(kb[1], 1); mb_init(kb[2], 1); }
    __syncthreads();

    auto issueKV = [&](int kt) {
        const int s = kt % 3;
        const uint32_t base = sKV + s * ASTG2;
        const int krow = b * SEQ + kt * 128;
        mb_expect(kb[s], ASTG2);
        tma2d(base,         &mQh, EMBED + h * HEAD_DIM,     krow, kb[s]);   // K (fp16 hi)
        tma2d(base + 16384, &mQh, 2 * EMBED + h * HEAD_DIM, krow, kb[s]);   // V (fp16 hi)
    };
    if (t == 0) {
        mb_expect(qb, 32768);
        tma2d(sQh, &mQh, h * HEAD_DIM, qrow, qb);
        tma2d(sQl, &mQl, h * HEAD_DIM, qrow, qb);
        issueKV(0); issueKV(1); issueKV(2);
    }

    uint32_t qfh[4][4], qfl[4][4];
    MBWAIT(qb, 0);
    #pragma unroll
    for (int ks = 0; ks < 4; ks++) {
        const int r = wid * 16 + (lane & 15);
        const int ch = 2 * ks + (lane >> 4);
        const uint32_t qd = (uint32_t)(r * 128 + ((ch ^ (r & 7)) << 4));
        ldsm4(qfh[ks], sQh + qd);
        ldsm4(qfl[ks], sQl + qd);
    }

    float o[8][4] = {};
    float m_lo = -1e30f, m_hi = -1e30f, l_lo = 0.0f, l_hi = 0.0f;

    const int NKV = SEQ / 128;
    for (int kt = 0; kt < NKV; kt++) {
        const int s = kt % 3;
        MBWAIT(kb[s], (kt / 3) & 1);
        const uint32_t base = sKV + s * ASTG2;
        const uint32_t aKh = base, aVh = base + 16384;

        // ---- S = Qh*K + Ql*K ----
        float sfr[16][4] = {};
        #pragma unroll
        for (int ks = 0; ks < 4; ks++) {
            uint32_t kd[16];
            #pragma unroll
            for (int j = 0; j < 16; j++) {
                const int r = j * 8 + (lane & 7);
                const int ch = 2 * ks + ((lane >> 3) & 1);
                kd[j] = (uint32_t)(r * 128 + ((ch ^ (r & 7)) << 4));
            }
            uint32_t kf[16][2];
            #pragma unroll
            for (int j = 0; j < 16; j++) ldsm2(kf[j], aKh + kd[j]);
            #pragma unroll
            for (int j = 0; j < 16; j++) mma16816h(sfr[j], qfh[ks], kf[j]);
            #pragma unroll
            for (int j = 0; j < 16; j++) mma16816h(sfr[j], qfl[ks], kf[j]);
        }

        // ---- online softmax ----
        float tmax_lo = -1e30f, tmax_hi = -1e30f;
        #pragma unroll
        for (int j = 0; j < 16; j++) {
            tmax_lo = fmaxf(tmax_lo, fmaxf(sfr[j][0], sfr[j][1]));
            tmax_hi = fmaxf(tmax_hi, fmaxf(sfr[j][2], sfr[j][3]));
        }
        tmax_lo = fmaxf(tmax_lo, __shfl_xor_sync(0xffffffffu, tmax_lo, 1));
        tmax_lo = fmaxf(tmax_lo, __shfl_xor_sync(0xffffffffu, tmax_lo, 2));
        tmax_hi = fmaxf(tmax_hi, __shfl_xor_sync(0xffffffffu, tmax_hi, 1));
        tmax_hi = fmaxf(tmax_hi, __shfl_xor_sync(0xffffffffu, tmax_hi, 2));
        float mn_lo = fmaxf(m_lo, tmax_lo), mn_hi = fmaxf(m_hi, tmax_hi);
        float corr_lo = __expf(m_lo - mn_lo), corr_hi = __expf(m_hi - mn_hi);
        m_lo = mn_lo; m_hi = mn_hi;

        float sum_lo = 0.0f, sum_hi = 0.0f;
        #pragma unroll
        for (int j = 0; j < 16; j++) {
            sfr[j][0] = __expf(sfr[j][0] - m_lo); sfr[j][1] = __expf(sfr[j][1] - m_lo);
            sfr[j][2] = __expf(sfr[j][2] - m_hi); sfr[j][3] = __expf(sfr[j][3] - m_hi);
            sum_lo += sfr[j][0] + sfr[j][1];
            sum_hi += sfr[j][2] + sfr[j][3];
        }
        sum_lo += __shfl_xor_sync(0xffffffffu, sum_lo, 1);
        sum_lo += __shfl_xor_sync(0xffffffffu, sum_lo, 2);
        sum_hi += __shfl_xor_sync(0xffffffffu, sum_hi, 1);
        sum_hi += __shfl_xor_sync(0xffffffffu, sum_hi, 2);
        l_lo = l_lo * corr_lo + sum_lo;
        l_hi = l_hi * corr_hi + sum_hi;
        #pragma unroll
        for (int j = 0; j < 8; j++) {
            o[j][0] *= corr_lo; o[j][1] *= corr_lo;
            o[j][2] *= corr_hi; o[j][3] *= corr_hi;
        }

        // ---- O += Ph*V + Pl*V ----
        #pragma unroll
        for (int kk = 0; kk < 8; kk++) {
            uint32_t ph[4], pl[4];
            split2h(sfr[2*kk  ][0], sfr[2*kk  ][1], ph[0], pl[0]);
            split2h(sfr[2*kk  ][2], sfr[2*kk  ][3], ph[1], pl[1]);
            split2h(sfr[2*kk+1][0], sfr[2*kk+1][1], ph[2], pl[2]);
            split2h(sfr[2*kk+1][2], sfr[2*kk+1][3], ph[3], pl[3]);

            const int r = kk * 16 + (lane & 15);
            uint32_t vf[8][2];
            #pragma unroll
            for (int j = 0; j < 8; j++)
                ldsm2t(vf[j], aVh + (uint32_t)(r * 128 + ((j ^ (r & 7)) << 4)));
            #pragma unroll
            for (int j = 0; j < 8; j++) mma16816h(o[j], ph, vf[j]);
            #pragma unroll
            for (int j = 0; j < 8; j++) mma16816h(o[j], pl, vf[j]);
        }
        __syncthreads();
        if (t == 0 && kt + 3 < NKV) issueKV(kt + 3);
    }

    // ---- epilogue: normalize + fp16 hi/lo out (proj GEMM A operand) ----
    const float inv_lo = 1.0f / l_lo, inv_hi = 1.0f / l_hi;
    const int r_lo = qt * 128 + wid * 16 + (lane >> 2);
    const size_t obase = (size_t)(b * SEQ) * EMBED + (size_t)h * HEAD_DIM;
    #pragma unroll
    for (int j = 0; j < 8; j++) {
        const int col = j * 8 + (lane & 3) * 2;
        uint32_t H, L;
        split2h(o[j][0] * inv_lo, o[j][1] * inv_lo, H, L);
        *(uint32_t*)&ohi[obase + (size_t)r_lo * EMBED + col] = H;
        *(uint32_t*)&olo[obase + (size_t)r_lo * EMBED + col] = L;
        split2h(o[j][2] * inv_hi, o[j][3] * inv_hi, H, L);
        *(uint32_t*)&ohi[obase + (size_t)(r_lo + 8) * EMBED + col] = H;
        *(uint32_t*)&olo[obase + (size_t)(r_lo + 8) * EMBED + col] = L;
    }
}

// ---------------------------------------------------------------------------
typedef CUresult (CUDAAPI *tmap_fn_t)(CUtensorMap*, CUtensorMapDataType, cuuint32_t,
    void*, const cuuint64_t*, const cuuint64_t*, const cuuint32_t*, const cuuint32_t*,
    CUtensorMapInterleave, CUtensorMapSwizzle, CUtensorMapL2promotion, CUtensorMapFloatOOBfill);

static void make_map(CUtensorMap* m, tmap_fn_t fn, void* base,
                     uint64_t cols, uint64_t rows)
{
    cuuint64_t dims[2]    = { cols, rows };
    cuuint64_t strides[1] = { cols * 2 };
    cuuint32_t box[2]     = { 64, 128 };
    cuuint32_t es[2]      = { 1, 1 };
    fn(m, CU_TENSOR_MAP_DATA_TYPE_BFLOAT16, 2, base, dims, strides, box, es,
       CU_TENSOR_MAP_INTERLEAVE_NONE, CU_TENSOR_MAP_SWIZZLE_128B,
       CU_TENSOR_MAP_L2_PROMOTION_L2_128B, CU_TENSOR_MAP_FLOAT_OOB_FILL_NONE);
}

extern "C" void kernel_launch(void* const* d_in, const int* in_sizes, int n_in,
                              void* d_out, int out_size)
{
    const float* x      = (const float*)d_in[0];
    const float* w_qkv  = (const float*)d_in[1];
    const float* b_qkv  = (const float*)d_in[2];
    const float* w_proj = (const float*)d_in[3];
    const float* b_proj = (const float*)d_in[4];
    float* out = (float*)d_out;

    __nv_bfloat16 *xhi, *xlo, *wqh, *wph, *qh, *ql, *ahi, *alo;
    cudaGetSymbolAddress((void**)&xhi, g_xhi);
    cudaGetSymbolAddress((void**)&xlo, g_xlo);
    cudaGetSymbolAddress((void**)&wqh, g_wqh);
    cudaGetSymbolAddress((void**)&wph, g_wph);
    cudaGetSymbolAddress((void**)&qh, g_qh);
    cudaGetSymbolAddress((void**)&ql, g_ql);
    cudaGetSymbolAddress((void**)&ahi, g_ahi);
    cudaGetSymbolAddress((void**)&alo, g_alo);

    tmap_fn_t fn = nullptr;
    cudaDriverEntryPointQueryResult qres;
    cudaGetDriverEntryPoint("cuTensorMapEncodeTiled", (void**)&fn,
                            cudaEnableDefault, &qres);

    static CUtensorMap mXh, mXl, mWq, mWp, mQh, mQl, mAh, mAl;
    make_map(&mXh, fn, xhi, EMBED,     MTOT);
    make_map(&mXl, fn, xlo, EMBED,     MTOT);
    make_map(&mWq, fn, wqh, EMBED,     3 * EMBED);
    make_map(&mWp, fn, wph, EMBED,     EMBED);
    make_map(&mQh, fn, qh,  3 * EMBED, MTOT);
    make_map(&mQl, fn, ql,  3 * EMBED, MTOT);
    make_map(&mAh, fn, ahi, EMBED,     MTOT);
    make_map(&mAl, fn, alo, EMBED,     MTOT);

    const int M = MTOT;
    cudaFuncSetAttribute(gemm_tma<0>, cudaFuncAttributeMaxDynamicSharedMemorySize, GSM);
    cudaFuncSetAttribute(gemm_tma<1>, cudaFuncAttributeMaxDynamicSharedMemorySize, GSM);
    cudaFuncSetAttribute(attn_tma,    cudaFuncAttributeMaxDynamicSharedMemorySize, ASM_BYTES);

    // fused splits (x -> fp16 hi/lo; weights -> single fp16)
    {
        const int total = N4_X + N4_WQ + N4_WP;
        split3_kernel<<<(total + 255) / 256, 256>>>(x, xhi, xlo,
                                                    w_qkv, wqh,
                                                    w_proj, wph);
    }

    // 1) QKV projection -> fp16 hi/lo (Q pre-scaled by 0.125)
    {
        dim3 g(3 * EMBED / 128, M / 128);
        gemm_tma<1><<<g, 512, GSM>>>(mXh, mXl, mWq, b_qkv,
                                     nullptr, qh, ql, M, 3 * EMBED, EMBED);
    }

    // 2) attention (fp16 2-mma scheme) -> fp16 hi/lo
    {
        dim3 g(SEQ / 128, HEADS, BATCH);
        attn_tma<<<g, 256, ASM_BYTES>>>(mQh, mQl, ahi, alo);
    }

    // 3) proj GEMM -> fp32 out
    {
        dim3 g(EMBED / 128, M / 128);
        gemm_tma<0><<<g, 512, GSM>>>(mAh, mAl, mWp, b_proj,
                                     out, nullptr, nullptr, M, EMBED, EMBED);
    }
}

// round 12
// speedup vs baseline: 1.5138x; 1.1453x over previous
#include <cuda_runtime.h>
#include <cuda.h>
#include <cuda_bf16.h>
#include <cuda_fp16.h>
#include <cstdint>

#define EMBED    1024
#define HEADS    16
#define HEAD_DIM 64
#define SEQ      2048
#define BATCH    2
#define MTOT     (BATCH * SEQ)    // 4096

// ------------------------------ scratch (TMA needs alignment) ---------------
// All 16-bit buffers hold fp16 bit patterns (declared bf16 for storage only).
__device__ __align__(1024) __nv_bfloat16 g_xhi[(size_t)MTOT * EMBED];
__device__ __align__(1024) __nv_bfloat16 g_xlo[(size_t)MTOT * EMBED];
__device__ __align__(1024) __nv_bfloat16 g_wqh[(size_t)3 * EMBED * EMBED];
__device__ __align__(1024) __nv_bfloat16 g_wph[(size_t)EMBED * EMBED];
__device__ __align__(1024) __nv_bfloat16 g_qh[(size_t)MTOT * 3 * EMBED];   // qkv single fp16
__device__ __align__(1024) __nv_bfloat16 g_ahi[(size_t)MTOT * EMBED];
__device__ __align__(1024) __nv_bfloat16 g_alo[(size_t)MTOT * EMBED];

// --------------------------- PTX helpers ------------------------------------
__device__ __forceinline__ uint32_t smem_u32(const void* p) {
    uint32_t a;
    asm("{ .reg .u64 t; cvta.to.shared.u64 t, %1; cvt.u32.u64 %0, t; }" : "=r"(a) : "l"(p));
    return a;
}
__device__ __forceinline__ void ldsm4(uint32_t* a, uint32_t addr) {
    asm volatile("ldmatrix.sync.aligned.m8n8.x4.shared.b16 {%0,%1,%2,%3}, [%4];"
                 : "=r"(a[0]), "=r"(a[1]), "=r"(a[2]), "=r"(a[3]) : "r"(addr));
}
__device__ __forceinline__ void ldsm2(uint32_t* b, uint32_t addr) {
    asm volatile("ldmatrix.sync.aligned.m8n8.x2.shared.b16 {%0,%1}, [%2];"
                 : "=r"(b[0]), "=r"(b[1]) : "r"(addr));
}
__device__ __forceinline__ void ldsm2t(uint32_t* b, uint32_t addr) {
    asm volatile("ldmatrix.sync.aligned.m8n8.x2.trans.shared.b16 {%0,%1}, [%2];"
                 : "=r"(b[0]), "=r"(b[1]) : "r"(addr));
}
__device__ __forceinline__ void mma16816h(float* c, const uint32_t* a, const uint32_t* b) {
    asm volatile(
        "mma.sync.aligned.m16n8k16.row.col.f32.f16.f16.f32 "
        "{%0,%1,%2,%3},{%4,%5,%6,%7},{%8,%9},{%0,%1,%2,%3};"
        : "+f"(c[0]), "+f"(c[1]), "+f"(c[2]), "+f"(c[3])
        : "r"(a[0]), "r"(a[1]), "r"(a[2]), "r"(a[3]), "r"(b[0]), "r"(b[1]));
}
__device__ __forceinline__ void tma2d(uint32_t s, const CUtensorMap* m, int x, int y, uint32_t mb) {
    asm volatile(
        "cp.async.bulk.tensor.2d.shared::cta.global.tile.mbarrier::complete_tx::bytes "
        "[%0], [%1, {%2, %3}], [%4];"
        :: "r"(s), "l"(m), "r"(x), "r"(y), "r"(mb) : "memory");
}
__device__ __forceinline__ void mb_init(uint32_t mb, uint32_t cnt) {
    asm volatile("mbarrier.init.shared.b64 [%0], %1;" :: "r"(mb), "r"(cnt) : "memory");
}
__device__ __forceinline__ void mb_expect(uint32_t mb, uint32_t bytes) {
    asm volatile("mbarrier.arrive.expect_tx.shared.b64 _, [%0], %1;" :: "r"(mb), "r"(bytes) : "memory");
}
#define MBWAIT(mb, ph)                                                          \
    asm volatile("{\n .reg .pred p;\nWL%=:\n"                                   \
                 " mbarrier.try_wait.parity.shared.b64 p, [%0], %1;\n"          \
                 " @!p bra WL%=;\n}"                                            \
                 :: "r"(mb), "r"((uint32_t)(ph)) : "memory")

// fp16 helpers
__device__ __forceinline__ uint32_t pack2h(float a, float b) {
    __half ha = __float2half_rn(a), hb = __float2half_rn(b);
    return ((uint32_t)__half_as_ushort(hb) << 16) | __half_as_ushort(ha);
}
__device__ __forceinline__ void split2h(float a, float b, uint32_t& H, uint32_t& L) {
    __half ha = __float2half_rn(a), hb = __float2half_rn(b);
    float la = a - __half2float(ha), lb = b - __half2float(hb);
    H = ((uint32_t)__half_as_ushort(hb) << 16) | __half_as_ushort(ha);
    L = pack2h(la, lb);
}

// ---- fp32 -> fp16: x as hi/lo pair; w_qkv, w_proj as single fp16 ------------
#define N4_X  (MTOT * EMBED / 4)
#define N4_WQ (3 * EMBED * EMBED / 4)
#define N4_WP (EMBED * EMBED / 4)

__global__ __launch_bounds__(256)
void split3_kernel(const float* __restrict__ x,  __nv_bfloat16* __restrict__ xh, __nv_bfloat16* __restrict__ xl,
                   const float* __restrict__ wq, __nv_bfloat16* __restrict__ wqh,
                   const float* __restrict__ wp, __nv_bfloat16* __restrict__ wph)
{
    int i = blockIdx.x * blockDim.x + threadIdx.x;
    if (i < N4_X) {
        float4 v = ((const float4*)x)[i];
        uint2 H, L;
        split2h(v.x, v.y, H.x, L.x);
        split2h(v.z, v.w, H.y, L.y);
        ((uint2*)xh)[i] = H;
        ((uint2*)xl)[i] = L;
        return;
    }
    const float* in; __nv_bfloat16* hi;
    if (i < N4_X + N4_WQ)              { in = wq; hi = wqh; i -= N4_X; }
    else if (i < N4_X + N4_WQ + N4_WP) { in = wp; hi = wph; i -= N4_X + N4_WQ; }
    else return;
    float4 v = ((const float4*)in)[i];
    uint2 H;
    H.x = pack2h(v.x, v.y);
    H.y = pack2h(v.z, v.w);
    ((uint2*)hi)[i] = H;
}

// ----------- TMA + fp16 2-term GEMM: C = A W^T + bias -----------------------
// A: fp16 hi+lo (exact). W: single fp16. C = Ah*W + Al*W.
// MODE 0: fp32 out. MODE 1: single fp16 out, cols < 1024 scaled by 0.125 (Q).
#define GSTG 49152                       // Ah + Al + B per stage (3 x 16KB)
#define GSM  (1024 + 3 * GSTG)

template<int MODE>
__global__ __launch_bounds__(512)
void gemm_tma(const __grid_constant__ CUtensorMap mAh,
              const __grid_constant__ CUtensorMap mAl,
              const __grid_constant__ CUtensorMap mB,
              const float* __restrict__ bias, float* __restrict__ C,
              __nv_bfloat16* __restrict__ Chi,
              int M, int N, int K)
{
    extern __shared__ char smem[];
    __shared__ uint64_t mbar[3];
    const uint32_t sb0 = (smem_u32(smem) + 1023) & ~1023u;

    const int t = threadIdx.x, lane = t & 31, wid = t >> 5;
    const int row0 = blockIdx.y * 128, col0 = blockIdx.x * 128;
    const int m0 = (wid >> 2) * 32, n0 = (wid & 3) * 32;

    uint32_t mb[3];
    #pragma unroll
    for (int s = 0; s < 3; s++) mb[s] = smem_u32(&mbar[s]);
    if (t == 0) {
        #pragma unroll
        for (int s = 0; s < 3; s++) mb_init(mb[s], 1);
    }
    __syncthreads();

    auto issue = [&](int kt) {
        const int s = kt % 3;
        const uint32_t base = sb0 + s * GSTG;
        mb_expect(mb[s], GSTG);
        tma2d(base,         &mAh, kt * 64, row0, mb[s]);
        tma2d(base + 16384, &mAl, kt * 64, row0, mb[s]);
        tma2d(base + 32768, &mB,  kt * 64, col0, mb[s]);
    };
    if (t == 0) { issue(0); issue(1); }

    float c[2][4][4] = {};
    const int KT = K / 64;

    for (int kt = 0; kt < KT; kt++) {
        if (t == 0 && kt + 2 < KT) issue(kt + 2);
        const int s = kt % 3;
        MBWAIT(mb[s], (kt / 3) & 1);
        const uint32_t base = sb0 + s * GSTG;
        const uint32_t aAh = base, aAl = base + 16384, aB = base + 32768;

        #pragma unroll
        for (int ks = 0; ks < 4; ks++) {
            uint32_t ad[2], bd[4];
            #pragma unroll
            for (int i = 0; i < 2; i++) {
                const int r = m0 + (lane & 15) + i * 16;
                const int ch = 2 * ks + (lane >> 4);
                ad[i] = (uint32_t)(r * 128 + ((ch ^ (r & 7)) << 4));
            }
            #pragma unroll
            for (int j = 0; j < 4; j++) {
                const int r = n0 + (lane & 7) + j * 8;
                const int ch = 2 * ks + ((lane >> 3) & 1);
                bd[j] = (uint32_t)(r * 128 + ((ch ^ (r & 7)) << 4));
            }
            uint32_t ah[2][4], al[2][4], bf[4][2];
            #pragma unroll
            for (int i = 0; i < 2; i++) ldsm4(ah[i], aAh + ad[i]);
            #pragma unroll
            for (int j = 0; j < 4; j++) ldsm2(bf[j], aB + bd[j]);
            #pragma unroll
            for (int i = 0; i < 2; i++)
                #pragma unroll
                for (int j = 0; j < 4; j++) mma16816h(c[i][j], ah[i], bf[j]);
            #pragma unroll
            for (int i = 0; i < 2; i++) ldsm4(al[i], aAl + ad[i]);
            #pragma unroll
            for (int i = 0; i < 2; i++)
                #pragma unroll
                for (int j = 0; j < 4; j++) mma16816h(c[i][j], al[i], bf[j]);
        }
        __syncthreads();
    }

    #pragma unroll
    for (int j = 0; j < 4; j++) {
        const int col = col0 + n0 + j * 8 + (lane & 3) * 2;
        const float2 bb = *(const float2*)&bias[col];
        const float sc = (MODE == 1 && col < EMBED) ? 0.125f : 1.0f;
        #pragma unroll
        for (int i = 0; i < 2; i++) {
            const int r0 = row0 + m0 + i * 16 + (lane >> 2);
            float v0 = (c[i][j][0] + bb.x) * sc, v1 = (c[i][j][1] + bb.y) * sc;
            float v2 = (c[i][j][2] + bb.x) * sc, v3 = (c[i][j][3] + bb.y) * sc;
            if (MODE == 0) {
                *(float2*)&C[(size_t)r0 * N + col]       = make_float2(v0, v1);
                *(float2*)&C[(size_t)(r0 + 8) * N + col] = make_float2(v2, v3);
            } else {
                *(uint32_t*)&Chi[(size_t)r0 * N + col]       = pack2h(v0, v1);
                *(uint32_t*)&Chi[(size_t)(r0 + 8) * N + col] = pack2h(v2, v3);
            }
        }
    }
}

// -------------- TMA + fp16 flash attention -----------------------------------
// Q, K, V: single fp16. S = Q*K (1 mma term); O = Ph*V + Pl*V (P split).
// 2-stage KV ring, 83 KB smem -> 2 CTAs/SM.
#define ASTG2 32768                           // Kh + Vh per stage
#define ASM_BYTES (1024 + 16384 + 2 * ASTG2)  // 82944

__global__ __launch_bounds__(256, 2)
void attn_tma(const __grid_constant__ CUtensorMap mQh,
              __nv_bfloat16* __restrict__ ohi, __nv_bfloat16* __restrict__ olo)
{
    extern __shared__ char smem[];
    __shared__ uint64_t mbar[3];   // [0]=Q, [1..2]=KV stages
    const uint32_t sb0 = (smem_u32(smem) + 1023) & ~1023u;
    const uint32_t sQh = sb0;
    const uint32_t sKV = sb0 + 16384;

    const int t = threadIdx.x, lane = t & 31, wid = t >> 5;
    const int qt = blockIdx.x, h = blockIdx.y, b = blockIdx.z;
    const int qrow = b * SEQ + qt * 128;

    uint32_t qb = smem_u32(&mbar[0]);
    uint32_t kb[2] = { smem_u32(&mbar[1]), smem_u32(&mbar[2]) };
    if (t == 0) { mb_init(qb, 1); mb_init(kb[0], 1); mb_init(kb[1], 1); }
    __syncthreads();

    auto issueKV = [&](int kt) {
        const int s = kt & 1;
        const uint32_t base = sKV + s * ASTG2;
        const int krow = b * SEQ + kt * 128;
        mb_expect(kb[s], ASTG2);
        tma2d(base,         &mQh, EMBED + h * HEAD_DIM,     krow, kb[s]);   // K
        tma2d(base + 16384, &mQh, 2 * EMBED + h * HEAD_DIM, krow, kb[s]);   // V
    };
    if (t == 0) {
        mb_expect(qb, 16384);
        tma2d(sQh, &mQh, h * HEAD_DIM, qrow, qb);
        issueKV(0); issueKV(1);
    }

    uint32_t qfh[4][4];
    MBWAIT(qb, 0);
    #pragma unroll
    for (int ks = 0; ks < 4; ks++) {
        const int r = wid * 16 + (lane & 15);
        const int ch = 2 * ks + (lane >> 4);
        const uint32_t qd = (uint32_t)(r * 128 + ((ch ^ (r & 7)) << 4));
        ldsm4(qfh[ks], sQh + qd);
    }

    float o[8][4] = {};
    float m_lo = -1e30f, m_hi = -1e30f, l_lo = 0.0f, l_hi = 0.0f;

    const int NKV = SEQ / 128;
    for (int kt = 0; kt < NKV; kt++) {
        const int s = kt & 1;
        MBWAIT(kb[s], (kt / 2) & 1);
        const uint32_t base = sKV + s * ASTG2;
        const uint32_t aKh = base, aVh = base + 16384;

        // ---- S = Q*K (1 term) ----
        float sfr[16][4] = {};
        #pragma unroll
        for (int ks = 0; ks < 4; ks++) {
            uint32_t kd[16];
            #pragma unroll
            for (int j = 0; j < 16; j++) {
                const int r = j * 8 + (lane & 7);
                const int ch = 2 * ks + ((lane >> 3) & 1);
                kd[j] = (uint32_t)(r * 128 + ((ch ^ (r & 7)) << 4));
            }
            uint32_t kf[16][2];
            #pragma unroll
            for (int j = 0; j < 16; j++) ldsm2(kf[j], aKh + kd[j]);
            #pragma unroll
            for (int j = 0; j < 16; j++) mma16816h(sfr[j], qfh[ks], kf[j]);
        }

        // ---- online softmax ----
        float tmax_lo = -1e30f, tmax_hi = -1e30f;
        #pragma unroll
        for (int j = 0; j < 16; j++) {
            tmax_lo = fmaxf(tmax_lo, fmaxf(sfr[j][0], sfr[j][1]));
            tmax_hi = fmaxf(tmax_hi, fmaxf(sfr[j][2], sfr[j][3]));
        }
        tmax_lo = fmaxf(tmax_lo, __shfl_xor_sync(0xffffffffu, tmax_lo, 1));
        tmax_lo = fmaxf(tmax_lo, __shfl_xor_sync(0xffffffffu, tmax_lo, 2));
        tmax_hi = fmaxf(tmax_hi, __shfl_xor_sync(0xffffffffu, tmax_hi, 1));
        tmax_hi = fmaxf(tmax_hi, __shfl_xor_sync(0xffffffffu, tmax_hi, 2));
        float mn_lo = fmaxf(m_lo, tmax_lo), mn_hi = fmaxf(m_hi, tmax_hi);
        float corr_lo = __expf(m_lo - mn_lo), corr_hi = __expf(m_hi - mn_hi);
        m_lo = mn_lo; m_hi = mn_hi;

        float sum_lo = 0.0f, sum_hi = 0.0f;
        #pragma unroll
        for (int j = 0; j < 16; j++) {
            sfr[j][0] = __expf(sfr[j][0] - m_lo); sfr[j][1] = __expf(sfr[j][1] - m_lo);
            sfr[j][2] = __expf(sfr[j][2] - m_hi); sfr[j][3] = __expf(sfr[j][3] - m_hi);
            sum_lo += sfr[j][0] + sfr[j][1];
            sum_hi += sfr[j][2] + sfr[j][3];
        }
        sum_lo += __shfl_xor_sync(0xffffffffu, sum_lo, 1);
        sum_lo += __shfl_xor_sync(0xffffffffu, sum_lo, 2);
        sum_hi += __shfl_xor_sync(0xffffffffu, sum_hi, 1);
        sum_hi += __shfl_xor_sync(0xffffffffu, sum_hi, 2);
        l_lo = l_lo * corr_lo + sum_lo;
        l_hi = l_hi * corr_hi + sum_hi;
        #pragma unroll
        for (int j = 0; j < 8; j++) {
            o[j][0] *= corr_lo; o[j][1] *= corr_lo;
            o[j][2] *= corr_hi; o[j][3] *= corr_hi;
        }

        // ---- O += Ph*V + Pl*V ----
        #pragma unroll
        for (int kk = 0; kk < 8; kk++) {
            uint32_t ph[4], pl[4];
            split2h(sfr[2*kk  ][0], sfr[2*kk  ][1], ph[0], pl[0]);
            split2h(sfr[2*kk  ][2], sfr[2*kk  ][3], ph[1], pl[1]);
            split2h(sfr[2*kk+1][0], sfr[2*kk+1][1], ph[2], pl[2]);
            split2h(sfr[2*kk+1][2], sfr[2*kk+1][3], ph[3], pl[3]);

            const int r = kk * 16 + (lane & 15);
            uint32_t vf[8][2];
            #pragma unroll
            for (int j = 0; j < 8; j++)
                ldsm2t(vf[j], aVh + (uint32_t)(r * 128 + ((j ^ (r & 7)) << 4)));
            #pragma unroll
            for (int j = 0; j < 8; j++) mma16816h(o[j], ph, vf[j]);
            #pragma unroll
            for (int j = 0; j < 8; j++) mma16816h(o[j], pl, vf[j]);
        }
        __syncthreads();
        if (t == 0 && kt + 2 < NKV) issueKV(kt + 2);
    }

    // ---- epilogue: normalize + fp16 hi/lo out (proj GEMM A operand) ----
    const float inv_lo = 1.0f / l_lo, inv_hi = 1.0f / l_hi;
    const int r_lo = qt * 128 + wid * 16 + (lane >> 2);
    const size_t obase = (size_t)(b * SEQ) * EMBED + (size_t)h * HEAD_DIM;
    #pragma unroll
    for (int j = 0; j < 8; j++) {
        const int col = j * 8 + (lane & 3) * 2;
        uint32_t H, L;
        split2h(o[j][0] * inv_lo, o[j][1] * inv_lo, H, L);
        *(uint32_t*)&ohi[obase + (size_t)r_lo * EMBED + col] = H;
        *(uint32_t*)&olo[obase + (size_t)r_lo * EMBED + col] = L;
        split2h(o[j][2] * inv_hi, o[j][3] * inv_hi, H, L);
        *(uint32_t*)&ohi[obase + (size_t)(r_lo + 8) * EMBED + col] = H;
        *(uint32_t*)&olo[obase + (size_t)(r_lo + 8) * EMBED + col] = L;
    }
}

// ---------------------------------------------------------------------------
typedef CUresult (CUDAAPI *tmap_fn_t)(CUtensorMap*, CUtensorMapDataType, cuuint32_t,
    void*, const cuuint64_t*, const cuuint64_t*, const cuuint32_t*, const cuuint32_t*,
    CUtensorMapInterleave, CUtensorMapSwizzle, CUtensorMapL2promotion, CUtensorMapFloatOOBfill);

static void make_map(CUtensorMap* m, tmap_fn_t fn, void* base,
                     uint64_t cols, uint64_t rows)
{
    cuuint64_t dims[2]    = { cols, rows };
    cuuint64_t strides[1] = { cols * 2 };
    cuuint32_t box[2]     = { 64, 128 };
    cuuint32_t es[2]      = { 1, 1 };
    fn(m, CU_TENSOR_MAP_DATA_TYPE_BFLOAT16, 2, base, dims, strides, box, es,
       CU_TENSOR_MAP_INTERLEAVE_NONE, CU_TENSOR_MAP_SWIZZLE_128B,
       CU_TENSOR_MAP_L2_PROMOTION_L2_128B, CU_TENSOR_MAP_FLOAT_OOB_FILL_NONE);
}

extern "C" void kernel_launch(void* const* d_in, const int* in_sizes, int n_in,
                              void* d_out, int out_size)
{
    const float* x      = (const float*)d_in[0];
    const float* w_qkv  = (const float*)d_in[1];
    const float* b_qkv  = (const float*)d_in[2];
    const float* w_proj = (const float*)d_in[3];
    const float* b_proj = (const float*)d_in[4];
    float* out = (float*)d_out;

    __nv_bfloat16 *xhi, *xlo, *wqh, *wph, *qh, *ahi, *alo;
    cudaGetSymbolAddress((void**)&xhi, g_xhi);
    cudaGetSymbolAddress((void**)&xlo, g_xlo);
    cudaGetSymbolAddress((void**)&wqh, g_wqh);
    cudaGetSymbolAddress((void**)&wph, g_wph);
    cudaGetSymbolAddress((void**)&qh, g_qh);
    cudaGetSymbolAddress((void**)&ahi, g_ahi);
    cudaGetSymbolAddress((void**)&alo, g_alo);

    tmap_fn_t fn = nullptr;
    cudaDriverEntryPointQueryResult qres;
    cudaGetDriverEntryPoint("cuTensorMapEncodeTiled", (void**)&fn,
                            cudaEnableDefault, &qres);

    static CUtensorMap mXh, mXl, mWq, mWp, mQh, mAh, mAl;
    make_map(&mXh, fn, xhi, EMBED,     MTOT);
    make_map(&mXl, fn, xlo, EMBED,     MTOT);
    make_map(&mWq, fn, wqh, EMBED,     3 * EMBED);
    make_map(&mWp, fn, wph, EMBED,     EMBED);
    make_map(&mQh, fn, qh,  3 * EMBED, MTOT);
    make_map(&mAh, fn, ahi, EMBED,     MTOT);
    make_map(&mAl, fn, alo, EMBED,     MTOT);

    const int M = MTOT;
    cudaFuncSetAttribute(gemm_tma<0>, cudaFuncAttributeMaxDynamicSharedMemorySize, GSM);
    cudaFuncSetAttribute(gemm_tma<1>, cudaFuncAttributeMaxDynamicSharedMemorySize, GSM);
    cudaFuncSetAttribute(attn_tma,    cudaFuncAttributeMaxDynamicSharedMemorySize, ASM_BYTES);

    // fused splits (x -> fp16 hi/lo; weights -> single fp16)
    {
        const int total = N4_X + N4_WQ + N4_WP;
        split3_kernel<<<(total + 255) / 256, 256>>>(x, xhi, xlo,
                                                    w_qkv, wqh,
                                                    w_proj, wph);
    }

    // 1) QKV projection -> single fp16 (Q pre-scaled by 0.125)
    {
        dim3 g(3 * EMBED / 128, M / 128);
        gemm_tma<1><<<g, 512, GSM>>>(mXh, mXl, mWq, b_qkv,
                                     nullptr, qh, M, 3 * EMBED, EMBED);
    }

    // 2) attention (fp16, 1-term QK / 2-term PV) -> fp16 hi/lo
    {
        dim3 g(SEQ / 128, HEADS, BATCH);
        attn_tma<<<g, 256, ASM_BYTES>>>(mQh, ahi, alo);
    }

    // 3) proj GEMM -> fp32 out
    {
        dim3 g(EMBED / 128, M / 128);
        gemm_tma<0><<<g, 512, GSM>>>(mAh, mAl, mWp, b_proj,
                                     out, nullptr, M, EMBED, EMBED);
    }
}

// round 13
// speedup vs baseline: 1.8996x; 1.2548x over previous
#include <cuda_runtime.h>
#include <cuda.h>
#include <cuda_bf16.h>
#include <cuda_fp16.h>
#include <cstdint>

#define EMBED    1024
#define HEADS    16
#define HEAD_DIM 64
#define SEQ      2048
#define BATCH    2
#define MTOT     (BATCH * SEQ)    // 4096

// ------------------------------ scratch (TMA needs alignment) ---------------
// All 16-bit buffers hold fp16 bit patterns (declared bf16 for storage only).
__device__ __align__(1024) __nv_bfloat16 g_xh[(size_t)MTOT * EMBED];
__device__ __align__(1024) __nv_bfloat16 g_wqh[(size_t)3 * EMBED * EMBED];
__device__ __align__(1024) __nv_bfloat16 g_wph[(size_t)EMBED * EMBED];
__device__ __align__(1024) __nv_bfloat16 g_qh[(size_t)MTOT * 3 * EMBED];   // qkv fp16
__device__ __align__(1024) __nv_bfloat16 g_ah[(size_t)MTOT * EMBED];       // attn out fp16

// --------------------------- PTX helpers ------------------------------------
__device__ __forceinline__ uint32_t smem_u32(const void* p) {
    uint32_t a;
    asm("{ .reg .u64 t; cvta.to.shared.u64 t, %1; cvt.u32.u64 %0, t; }" : "=r"(a) : "l"(p));
    return a;
}
__device__ __forceinline__ void ldsm4(uint32_t* a, uint32_t addr) {
    asm volatile("ldmatrix.sync.aligned.m8n8.x4.shared.b16 {%0,%1,%2,%3}, [%4];"
                 : "=r"(a[0]), "=r"(a[1]), "=r"(a[2]), "=r"(a[3]) : "r"(addr));
}
__device__ __forceinline__ void ldsm2(uint32_t* b, uint32_t addr) {
    asm volatile("ldmatrix.sync.aligned.m8n8.x2.shared.b16 {%0,%1}, [%2];"
                 : "=r"(b[0]), "=r"(b[1]) : "r"(addr));
}
__device__ __forceinline__ void ldsm2t(uint32_t* b, uint32_t addr) {
    asm volatile("ldmatrix.sync.aligned.m8n8.x2.trans.shared.b16 {%0,%1}, [%2];"
                 : "=r"(b[0]), "=r"(b[1]) : "r"(addr));
}
__device__ __forceinline__ void mma16816h(float* c, const uint32_t* a, const uint32_t* b) {
    asm volatile(
        "mma.sync.aligned.m16n8k16.row.col.f32.f16.f16.f32 "
        "{%0,%1,%2,%3},{%4,%5,%6,%7},{%8,%9},{%0,%1,%2,%3};"
        : "+f"(c[0]), "+f"(c[1]), "+f"(c[2]), "+f"(c[3])
        : "r"(a[0]), "r"(a[1]), "r"(a[2]), "r"(a[3]), "r"(b[0]), "r"(b[1]));
}
__device__ __forceinline__ void tma2d(uint32_t s, const CUtensorMap* m, int x, int y, uint32_t mb) {
    asm volatile(
        "cp.async.bulk.tensor.2d.shared::cta.global.tile.mbarrier::complete_tx::bytes "
        "[%0], [%1, {%2, %3}], [%4];"
        :: "r"(s), "l"(m), "r"(x), "r"(y), "r"(mb) : "memory");
}
__device__ __forceinline__ void mb_init(uint32_t mb, uint32_t cnt) {
    asm volatile("mbarrier.init.shared.b64 [%0], %1;" :: "r"(mb), "r"(cnt) : "memory");
}
__device__ __forceinline__ void mb_expect(uint32_t mb, uint32_t bytes) {
    asm volatile("mbarrier.arrive.expect_tx.shared.b64 _, [%0], %1;" :: "r"(mb), "r"(bytes) : "memory");
}
#define MBWAIT(mb, ph)                                                          \
    asm volatile("{\n .reg .pred p;\nWL%=:\n"                                   \
                 " mbarrier.try_wait.parity.shared.b64 p, [%0], %1;\n"          \
                 " @!p bra WL%=;\n}"                                            \
                 :: "r"(mb), "r"((uint32_t)(ph)) : "memory")

// fp16 helpers
__device__ __forceinline__ uint32_t pack2h(float a, float b) {
    __half ha = __float2half_rn(a), hb = __float2half_rn(b);
    return ((uint32_t)__half_as_ushort(hb) << 16) | __half_as_ushort(ha);
}
__device__ __forceinline__ void split2h(float a, float b, uint32_t& H, uint32_t& L) {
    __half ha = __float2half_rn(a), hb = __float2half_rn(b);
    float la = a - __half2float(ha), lb = b - __half2float(hb);
    H = ((uint32_t)__half_as_ushort(hb) << 16) | __half_as_ushort(ha);
    L = pack2h(la, lb);
}

// ---- fp32 -> single fp16 convert: x, w_qkv, w_proj in one launch ------------
#define N4_X  (MTOT * EMBED / 4)
#define N4_WQ (3 * EMBED * EMBED / 4)
#define N4_WP (EMBED * EMBED / 4)

__global__ __launch_bounds__(256)
void cvt3_kernel(const float* __restrict__ x,  __nv_bfloat16* __restrict__ xh,
                 const float* __restrict__ wq, __nv_bfloat16* __restrict__ wqh,
                 const float* __restrict__ wp, __nv_bfloat16* __restrict__ wph)
{
    int i = blockIdx.x * blockDim.x + threadIdx.x;
    const float* in; __nv_bfloat16* hi;
    if (i < N4_X)                      { in = x;  hi = xh; }
    else if (i < N4_X + N4_WQ)         { in = wq; hi = wqh; i -= N4_X; }
    else if (i < N4_X + N4_WQ + N4_WP) { in = wp; hi = wph; i -= N4_X + N4_WQ; }
    else return;
    float4 v = ((const float4*)in)[i];
    uint2 H;
    H.x = pack2h(v.x, v.y);
    H.y = pack2h(v.z, v.w);
    ((uint2*)hi)[i] = H;
}

// ----------- TMA + fp16 1-term GEMM: C = A W^T + bias -----------------------
// A: single fp16. W: single fp16. C = A*W.
// MODE 0: fp32 out. MODE 1: single fp16 out, cols < 1024 scaled by 0.125 (Q).
#define GSTG 32768                       // A + B per stage (2 x 16KB)
#define GSM  (1024 + 3 * GSTG)           // 99328

template<int MODE>
__global__ __launch_bounds__(512, 2)
void gemm_tma(const __grid_constant__ CUtensorMap mA,
              const __grid_constant__ CUtensorMap mB,
              const float* __restrict__ bias, float* __restrict__ C,
              __nv_bfloat16* __restrict__ Chi,
              int M, int N, int K)
{
    extern __shared__ char smem[];
    __shared__ uint64_t mbar[3];
    const uint32_t sb0 = (smem_u32(smem) + 1023) & ~1023u;

    const int t = threadIdx.x, lane = t & 31, wid = t >> 5;
    const int row0 = blockIdx.y * 128, col0 = blockIdx.x * 128;
    const int m0 = (wid >> 2) * 32, n0 = (wid & 3) * 32;

    uint32_t mb[3];
    #pragma unroll
    for (int s = 0; s < 3; s++) mb[s] = smem_u32(&mbar[s]);
    if (t == 0) {
        #pragma unroll
        for (int s = 0; s < 3; s++) mb_init(mb[s], 1);
    }
    __syncthreads();

    auto issue = [&](int kt) {
        const int s = kt % 3;
        const uint32_t base = sb0 + s * GSTG;
        mb_expect(mb[s], GSTG);
        tma2d(base,         &mA, kt * 64, row0, mb[s]);
        tma2d(base + 16384, &mB, kt * 64, col0, mb[s]);
    };
    if (t == 0) { issue(0); issue(1); }

    float c[2][4][4] = {};
    const int KT = K / 64;

    for (int kt = 0; kt < KT; kt++) {
        if (t == 0 && kt + 2 < KT) issue(kt + 2);
        const int s = kt % 3;
        MBWAIT(mb[s], (kt / 3) & 1);
        const uint32_t base = sb0 + s * GSTG;
        const uint32_t aA = base, aB = base + 16384;

        #pragma unroll
        for (int ks = 0; ks < 4; ks++) {
            uint32_t ad[2], bd[4];
            #pragma unroll
            for (int i = 0; i < 2; i++) {
                const int r = m0 + (lane & 15) + i * 16;
                const int ch = 2 * ks + (lane >> 4);
                ad[i] = (uint32_t)(r * 128 + ((ch ^ (r & 7)) << 4));
            }
            #pragma unroll
            for (int j = 0; j < 4; j++) {
                const int r = n0 + (lane & 7) + j * 8;
                const int ch = 2 * ks + ((lane >> 3) & 1);
                bd[j] = (uint32_t)(r * 128 + ((ch ^ (r & 7)) << 4));
            }
            uint32_t af[2][4], bf[4][2];
            #pragma unroll
            for (int i = 0; i < 2; i++) ldsm4(af[i], aA + ad[i]);
            #pragma unroll
            for (int j = 0; j < 4; j++) ldsm2(bf[j], aB + bd[j]);
            #pragma unroll
            for (int i = 0; i < 2; i++)
                #pragma unroll
                for (int j = 0; j < 4; j++) mma16816h(c[i][j], af[i], bf[j]);
        }
        __syncthreads();
    }

    #pragma unroll
    for (int j = 0; j < 4; j++) {
        const int col = col0 + n0 + j * 8 + (lane & 3) * 2;
        const float2 bb = *(const float2*)&bias[col];
        const float sc = (MODE == 1 && col < EMBED) ? 0.125f : 1.0f;
        #pragma unroll
        for (int i = 0; i < 2; i++) {
            const int r0 = row0 + m0 + i * 16 + (lane >> 2);
            float v0 = (c[i][j][0] + bb.x) * sc, v1 = (c[i][j][1] + bb.y) * sc;
            float v2 = (c[i][j][2] + bb.x) * sc, v3 = (c[i][j][3] + bb.y) * sc;
            if (MODE == 0) {
                *(float2*)&C[(size_t)r0 * N + col]       = make_float2(v0, v1);
                *(float2*)&C[(size_t)(r0 + 8) * N + col] = make_float2(v2, v3);
            } else {
                *(uint32_t*)&Chi[(size_t)r0 * N + col]       = pack2h(v0, v1);
                *(uint32_t*)&Chi[(size_t)(r0 + 8) * N + col] = pack2h(v2, v3);
            }
        }
    }
}

// -------------- TMA + fp16 flash attention -----------------------------------
// Q, K, V: single fp16. S = Q*K (1 mma term); O = Ph*V + Pl*V (P split).
// 2-stage KV ring, 83 KB smem -> 2 CTAs/SM.
#define ASTG2 32768                           // K + V per stage
#define ASM_BYTES (1024 + 16384 + 2 * ASTG2)  // 82944

__global__ __launch_bounds__(256, 2)
void attn_tma(const __grid_constant__ CUtensorMap mQh,
              __nv_bfloat16* __restrict__ oh)
{
    extern __shared__ char smem[];
    __shared__ uint64_t mbar[3];   // [0]=Q, [1..2]=KV stages
    const uint32_t sb0 = (smem_u32(smem) + 1023) & ~1023u;
    const uint32_t sQh = sb0;
    const uint32_t sKV = sb0 + 16384;

    const int t = threadIdx.x, lane = t & 31, wid = t >> 5;
    const int qt = blockIdx.x, h = blockIdx.y, b = blockIdx.z;
    const int qrow = b * SEQ + qt * 128;

    uint32_t qb = smem_u32(&mbar[0]);
    uint32_t kb[2] = { smem_u32(&mbar[1]), smem_u32(&mbar[2]) };
    if (t == 0) { mb_init(qb, 1); mb_init(kb[0], 1); mb_init(kb[1], 1); }
    __syncthreads();

    auto issueKV = [&](int kt) {
        const int s = kt & 1;
        const uint32_t base = sKV + s * ASTG2;
        const int krow = b * SEQ + kt * 128;
        mb_expect(kb[s], ASTG2);
        tma2d(base,         &mQh, EMBED + h * HEAD_DIM,     krow, kb[s]);   // K
        tma2d(base + 16384, &mQh, 2 * EMBED + h * HEAD_DIM, krow, kb[s]);   // V
    };
    if (t == 0) {
        mb_expect(qb, 16384);
        tma2d(sQh, &mQh, h * HEAD_DIM, qrow, qb);
        issueKV(0); issueKV(1);
    }

    uint32_t qfh[4][4];
    MBWAIT(qb, 0);
    #pragma unroll
    for (int ks = 0; ks < 4; ks++) {
        const int r = wid * 16 + (lane & 15);
        const int ch = 2 * ks + (lane >> 4);
        const uint32_t qd = (uint32_t)(r * 128 + ((ch ^ (r & 7)) << 4));
        ldsm4(qfh[ks], sQh + qd);
    }

    float o[8][4] = {};
    float m_lo = -1e30f, m_hi = -1e30f, l_lo = 0.0f, l_hi = 0.0f;

    const int NKV = SEQ / 128;
    for (int kt = 0; kt < NKV; kt++) {
        const int s = kt & 1;
        MBWAIT(kb[s], (kt / 2) & 1);
        const uint32_t base = sKV + s * ASTG2;
        const uint32_t aKh = base, aVh = base + 16384;

        // ---- S = Q*K (1 term) ----
        float sfr[16][4] = {};
        #pragma unroll
        for (int ks = 0; ks < 4; ks++) {
            uint32_t kd[16];
            #pragma unroll
            for (int j = 0; j < 16; j++) {
                const int r = j * 8 + (lane & 7);
                const int ch = 2 * ks + ((lane >> 3) & 1);
                kd[j] = (uint32_t)(r * 128 + ((ch ^ (r & 7)) << 4));
            }
            uint32_t kf[16][2];
            #pragma unroll
            for (int j = 0; j < 16; j++) ldsm2(kf[j], aKh + kd[j]);
            #pragma unroll
            for (int j = 0; j < 16; j++) mma16816h(sfr[j], qfh[ks], kf[j]);
        }

        // ---- online softmax ----
        float tmax_lo = -1e30f, tmax_hi = -1e30f;
        #pragma unroll
        for (int j = 0; j < 16; j++) {
            tmax_lo = fmaxf(tmax_lo, fmaxf(sfr[j][0], sfr[j][1]));
            tmax_hi = fmaxf(tmax_hi, fmaxf(sfr[j][2], sfr[j][3]));
        }
        tmax_lo = fmaxf(tmax_lo, __shfl_xor_sync(0xffffffffu, tmax_lo, 1));
        tmax_lo = fmaxf(tmax_lo, __shfl_xor_sync(0xffffffffu, tmax_lo, 2));
        tmax_hi = fmaxf(tmax_hi, __shfl_xor_sync(0xffffffffu, tmax_hi, 1));
        tmax_hi = fmaxf(tmax_hi, __shfl_xor_sync(0xffffffffu, tmax_hi, 2));
        float mn_lo = fmaxf(m_lo, tmax_lo), mn_hi = fmaxf(m_hi, tmax_hi);
        float corr_lo = __expf(m_lo - mn_lo), corr_hi = __expf(m_hi - mn_hi);
        m_lo = mn_lo; m_hi = mn_hi;

        float sum_lo = 0.0f, sum_hi = 0.0f;
        #pragma unroll
        for (int j = 0; j < 16; j++) {
            sfr[j][0] = __expf(sfr[j][0] - m_lo); sfr[j][1] = __expf(sfr[j][1] - m_lo);
            sfr[j][2] = __expf(sfr[j][2] - m_hi); sfr[j][3] = __expf(sfr[j][3] - m_hi);
            sum_lo += sfr[j][0] + sfr[j][1];
            sum_hi += sfr[j][2] + sfr[j][3];
        }
        sum_lo += __shfl_xor_sync(0xffffffffu, sum_lo, 1);
        sum_lo += __shfl_xor_sync(0xffffffffu, sum_lo, 2);
        sum_hi += __shfl_xor_sync(0xffffffffu, sum_hi, 1);
        sum_hi += __shfl_xor_sync(0xffffffffu, sum_hi, 2);
        l_lo = l_lo * corr_lo + sum_lo;
        l_hi = l_hi * corr_hi + sum_hi;
        #pragma unroll
        for (int j = 0; j < 8; j++) {
            o[j][0] *= corr_lo; o[j][1] *= corr_lo;
            o[j][2] *= corr_hi; o[j][3] *= corr_hi;
        }

        // ---- O += Ph*V + Pl*V ----
        #pragma unroll
        for (int kk = 0; kk < 8; kk++) {
            uint32_t ph[4], pl[4];
            split2h(sfr[2*kk  ][0], sfr[2*kk  ][1], ph[0], pl[0]);
            split2h(sfr[2*kk  ][2], sfr[2*kk  ][3], ph[1], pl[1]);
            split2h(sfr[2*kk+1][0], sfr[2*kk+1][1], ph[2], pl[2]);
            split2h(sfr[2*kk+1][2], sfr[2*kk+1][3], ph[3], pl[3]);

            const int r = kk * 16 + (lane & 15);
            uint32_t vf[8][2];
            #pragma unroll
            for (int j = 0; j < 8; j++)
                ldsm2t(vf[j], aVh + (uint32_t)(r * 128 + ((j ^ (r & 7)) << 4)));
            #pragma unroll
            for (int j = 0; j < 8; j++) mma16816h(o[j], ph, vf[j]);
            #pragma unroll
            for (int j = 0; j < 8; j++) mma16816h(o[j], pl, vf[j]);
        }
        __syncthreads();
        if (t == 0 && kt + 2 < NKV) issueKV(kt + 2);
    }

    // ---- epilogue: normalize + single fp16 out (proj GEMM A operand) ----
    const float inv_lo = 1.0f / l_lo, inv_hi = 1.0f / l_hi;
    const int r_lo = qt * 128 + wid * 16 + (lane >> 2);
    const size_t obase = (size_t)(b * SEQ) * EMBED + (size_t)h * HEAD_DIM;
    #pragma unroll
    for (int j = 0; j < 8; j++) {
        const int col = j * 8 + (lane & 3) * 2;
        *(uint32_t*)&oh[obase + (size_t)r_lo * EMBED + col] =
            pack2h(o[j][0] * inv_lo, o[j][1] * inv_lo);
        *(uint32_t*)&oh[obase + (size_t)(r_lo + 8) * EMBED + col] =
            pack2h(o[j][2] * inv_hi, o[j][3] * inv_hi);
    }
}

// ---------------------------------------------------------------------------
typedef CUresult (CUDAAPI *tmap_fn_t)(CUtensorMap*, CUtensorMapDataType, cuuint32_t,
    void*, const cuuint64_t*, const cuuint64_t*, const cuuint32_t*, const cuuint32_t*,
    CUtensorMapInterleave, CUtensorMapSwizzle, CUtensorMapL2promotion, CUtensorMapFloatOOBfill);

static void make_map(CUtensorMap* m, tmap_fn_t fn, void* base,
                     uint64_t cols, uint64_t rows)
{
    cuuint64_t dims[2]    = { cols, rows };
    cuuint64_t strides[1] = { cols * 2 };
    cuuint32_t box[2]     = { 64, 128 };
    cuuint32_t es[2]      = { 1, 1 };
    fn(m, CU_TENSOR_MAP_DATA_TYPE_BFLOAT16, 2, base, dims, strides, box, es,
       CU_TENSOR_MAP_INTERLEAVE_NONE, CU_TENSOR_MAP_SWIZZLE_128B,
       CU_TENSOR_MAP_L2_PROMOTION_L2_128B, CU_TENSOR_MAP_FLOAT_OOB_FILL_NONE);
}

extern "C" void kernel_launch(void* const* d_in, const int* in_sizes, int n_in,
                              void* d_out, int out_size)
{
    const float* x      = (const float*)d_in[0];
    const float* w_qkv  = (const float*)d_in[1];
    const float* b_qkv  = (const float*)d_in[2];
    const float* w_proj = (const float*)d_in[3];
    const float* b_proj = (const float*)d_in[4];
    float* out = (float*)d_out;

    __nv_bfloat16 *xh, *wqh, *wph, *qh, *ah;
    cudaGetSymbolAddress((void**)&xh, g_xh);
    cudaGetSymbolAddress((void**)&wqh, g_wqh);
    cudaGetSymbolAddress((void**)&wph, g_wph);
    cudaGetSymbolAddress((void**)&qh, g_qh);
    cudaGetSymbolAddress((void**)&ah, g_ah);

    tmap_fn_t fn = nullptr;
    cudaDriverEntryPointQueryResult qres;
    cudaGetDriverEntryPoint("cuTensorMapEncodeTiled", (void**)&fn,
                            cudaEnableDefault, &qres);

    static CUtensorMap mX, mWq, mWp, mQh, mA;
    make_map(&mX,  fn, xh,  EMBED,     MTOT);
    make_map(&mWq, fn, wqh, EMBED,     3 * EMBED);
    make_map(&mWp, fn, wph, EMBED,     EMBED);
    make_map(&mQh, fn, qh,  3 * EMBED, MTOT);
    make_map(&mA,  fn, ah,  EMBED,     MTOT);

    const int M = MTOT;
    cudaFuncSetAttribute(gemm_tma<0>, cudaFuncAttributeMaxDynamicSharedMemorySize, GSM);
    cudaFuncSetAttribute(gemm_tma<1>, cudaFuncAttributeMaxDynamicSharedMemorySize, GSM);
    cudaFuncSetAttribute(attn_tma,    cudaFuncAttributeMaxDynamicSharedMemorySize, ASM_BYTES);

    // fused fp32 -> fp16 converts (x, w_qkv, w_proj)
    {
        const int total = N4_X + N4_WQ + N4_WP;
        cvt3_kernel<<<(total + 255) / 256, 256>>>(x, xh, w_qkv, wqh, w_proj, wph);
    }

    // 1) QKV projection -> single fp16 (Q pre-scaled by 0.125)
    {
        dim3 g(3 * EMBED / 128, M / 128);
        gemm_tma<1><<<g, 512, GSM>>>(mX, mWq, b_qkv, nullptr, qh,
                                     M, 3 * EMBED, EMBED);
    }

    // 2) attention (fp16, 1-term QK / 2-term PV) -> single fp16
    {
        dim3 g(SEQ / 128, HEADS, BATCH);
        attn_tma<<<g, 256, ASM_BYTES>>>(mQh, ah);
    }

    // 3) proj GEMM -> fp32 out
    {
        dim3 g(EMBED / 128, M / 128);
        gemm_tma<0><<<g, 512, GSM>>>(mA, mWp, b_proj, out, nullptr,
                                     M, EMBED, EMBED);
    }
}

// round 14
// speedup vs baseline: 2.2730x; 1.1965x over previous
#include <cuda_runtime.h>
#include <cuda.h>
#include <cuda_bf16.h>
#include <cuda_fp16.h>
#include <cstdint>

#define EMBED    1024
#define HEADS    16
#define HEAD_DIM 64
#define SEQ      2048
#define BATCH    2
#define MTOT     (BATCH * SEQ)    // 4096

// ------------------------------ scratch (TMA needs alignment) ---------------
// All 16-bit buffers hold fp16 bit patterns (declared bf16 for storage only).
__device__ __align__(1024) __nv_bfloat16 g_xh[(size_t)MTOT * EMBED];
__device__ __align__(1024) __nv_bfloat16 g_wqh[(size_t)3 * EMBED * EMBED];
__device__ __align__(1024) __nv_bfloat16 g_wph[(size_t)EMBED * EMBED];
__device__ __align__(1024) __nv_bfloat16 g_qh[(size_t)MTOT * 3 * EMBED];   // qkv fp16
__device__ __align__(1024) __nv_bfloat16 g_ah[(size_t)MTOT * EMBED];       // attn out fp16

// --------------------------- PTX helpers ------------------------------------
__device__ __forceinline__ uint32_t smem_u32(const void* p) {
    uint32_t a;
    asm("{ .reg .u64 t; cvta.to.shared.u64 t, %1; cvt.u32.u64 %0, t; }" : "=r"(a) : "l"(p));
    return a;
}
__device__ __forceinline__ void ldsm4(uint32_t* a, uint32_t addr) {
    asm volatile("ldmatrix.sync.aligned.m8n8.x4.shared.b16 {%0,%1,%2,%3}, [%4];"
                 : "=r"(a[0]), "=r"(a[1]), "=r"(a[2]), "=r"(a[3]) : "r"(addr));
}
__device__ __forceinline__ void ldsm2(uint32_t* b, uint32_t addr) {
    asm volatile("ldmatrix.sync.aligned.m8n8.x2.shared.b16 {%0,%1}, [%2];"
                 : "=r"(b[0]), "=r"(b[1]) : "r"(addr));
}
__device__ __forceinline__ void ldsm2t(uint32_t* b, uint32_t addr) {
    asm volatile("ldmatrix.sync.aligned.m8n8.x2.trans.shared.b16 {%0,%1}, [%2];"
                 : "=r"(b[0]), "=r"(b[1]) : "r"(addr));
}
__device__ __forceinline__ void mma16816h(float* c, const uint32_t* a, const uint32_t* b) {
    asm volatile(
        "mma.sync.aligned.m16n8k16.row.col.f32.f16.f16.f32 "
        "{%0,%1,%2,%3},{%4,%5,%6,%7},{%8,%9},{%0,%1,%2,%3};"
        : "+f"(c[0]), "+f"(c[1]), "+f"(c[2]), "+f"(c[3])
        : "r"(a[0]), "r"(a[1]), "r"(a[2]), "r"(a[3]), "r"(b[0]), "r"(b[1]));
}
__device__ __forceinline__ void tma2d(uint32_t s, const CUtensorMap* m, int x, int y, uint32_t mb) {
    asm volatile(
        "cp.async.bulk.tensor.2d.shared::cta.global.tile.mbarrier::complete_tx::bytes "
        "[%0], [%1, {%2, %3}], [%4];"
        :: "r"(s), "l"(m), "r"(x), "r"(y), "r"(mb) : "memory");
}
__device__ __forceinline__ void mb_init(uint32_t mb, uint32_t cnt) {
    asm volatile("mbarrier.init.shared.b64 [%0], %1;" :: "r"(mb), "r"(cnt) : "memory");
}
__device__ __forceinline__ void mb_expect(uint32_t mb, uint32_t bytes) {
    asm volatile("mbarrier.arrive.expect_tx.shared.b64 _, [%0], %1;" :: "r"(mb), "r"(bytes) : "memory");
}
#define MBWAIT(mb, ph)                                                          \
    asm volatile("{\n .reg .pred p;\nWL%=:\n"                                   \
                 " mbarrier.try_wait.parity.shared.b64 p, [%0], %1;\n"          \
                 " @!p bra WL%=;\n}"                                            \
                 :: "r"(mb), "r"((uint32_t)(ph)) : "memory")

// fp16 helpers
__device__ __forceinline__ uint32_t pack2h(float a, float b) {
    __half ha = __float2half_rn(a), hb = __float2half_rn(b);
    return ((uint32_t)__half_as_ushort(hb) << 16) | __half_as_ushort(ha);
}

// ---- fp32 -> single fp16 convert: x, w_qkv, w_proj in one launch ------------
#define N4_X  (MTOT * EMBED / 4)
#define N4_WQ (3 * EMBED * EMBED / 4)
#define N4_WP (EMBED * EMBED / 4)

__global__ __launch_bounds__(256)
void cvt3_kernel(const float* __restrict__ x,  __nv_bfloat16* __restrict__ xh,
                 const float* __restrict__ wq, __nv_bfloat16* __restrict__ wqh,
                 const float* __restrict__ wp, __nv_bfloat16* __restrict__ wph)
{
    int i = blockIdx.x * blockDim.x + threadIdx.x;
    const float* in; __nv_bfloat16* hi;
    if (i < N4_X)                      { in = x;  hi = xh; }
    else if (i < N4_X + N4_WQ)         { in = wq; hi = wqh; i -= N4_X; }
    else if (i < N4_X + N4_WQ + N4_WP) { in = wp; hi = wph; i -= N4_X + N4_WQ; }
    else return;
    float4 v = ((const float4*)in)[i];
    uint2 H;
    H.x = pack2h(v.x, v.y);
    H.y = pack2h(v.z, v.w);
    ((uint2*)hi)[i] = H;
}

// ----------- TMA + fp16 1-term GEMM: C = A W^T + bias -----------------------
// MODE 0: fp32 out. MODE 1: single fp16 out, cols < 1024 scaled by 0.125 (Q).
#define GSTG 32768                       // A + B per stage (2 x 16KB)
#define GSM  (1024 + 3 * GSTG)           // 99328

template<int MODE>
__global__ __launch_bounds__(512, 2)
void gemm_tma(const __grid_constant__ CUtensorMap mA,
              const __grid_constant__ CUtensorMap mB,
              const float* __restrict__ bias, float* __restrict__ C,
              __nv_bfloat16* __restrict__ Chi,
              int M, int N, int K)
{
    extern __shared__ char smem[];
    __shared__ uint64_t mbar[3];
    const uint32_t sb0 = (smem_u32(smem) + 1023) & ~1023u;

    const int t = threadIdx.x, lane = t & 31, wid = t >> 5;
    const int row0 = blockIdx.y * 128, col0 = blockIdx.x * 128;
    const int m0 = (wid >> 2) * 32, n0 = (wid & 3) * 32;

    uint32_t mb[3];
    #pragma unroll
    for (int s = 0; s < 3; s++) mb[s] = smem_u32(&mbar[s]);
    if (t == 0) {
        #pragma unroll
        for (int s = 0; s < 3; s++) mb_init(mb[s], 1);
    }
    __syncthreads();

    auto issue = [&](int kt) {
        const int s = kt % 3;
        const uint32_t base = sb0 + s * GSTG;
        mb_expect(mb[s], GSTG);
        tma2d(base,         &mA, kt * 64, row0, mb[s]);
        tma2d(base + 16384, &mB, kt * 64, col0, mb[s]);
    };
    if (t == 0) { issue(0); issue(1); }

    float c[2][4][4] = {};
    const int KT = K / 64;

    for (int kt = 0; kt < KT; kt++) {
        if (t == 0 && kt + 2 < KT) issue(kt + 2);
        const int s = kt % 3;
        MBWAIT(mb[s], (kt / 3) & 1);
        const uint32_t base = sb0 + s * GSTG;
        const uint32_t aA = base, aB = base + 16384;

        #pragma unroll
        for (int ks = 0; ks < 4; ks++) {
            uint32_t ad[2], bd[4];
            #pragma unroll
            for (int i = 0; i < 2; i++) {
                const int r = m0 + (lane & 15) + i * 16;
                const int ch = 2 * ks + (lane >> 4);
                ad[i] = (uint32_t)(r * 128 + ((ch ^ (r & 7)) << 4));
            }
            #pragma unroll
            for (int j = 0; j < 4; j++) {
                const int r = n0 + (lane & 7) + j * 8;
                const int ch = 2 * ks + ((lane >> 3) & 1);
                bd[j] = (uint32_t)(r * 128 + ((ch ^ (r & 7)) << 4));
            }
            uint32_t af[2][4], bf[4][2];
            #pragma unroll
            for (int i = 0; i < 2; i++) ldsm4(af[i], aA + ad[i]);
            #pragma unroll
            for (int j = 0; j < 4; j++) ldsm2(bf[j], aB + bd[j]);
            #pragma unroll
            for (int i = 0; i < 2; i++)
                #pragma unroll
                for (int j = 0; j < 4; j++) mma16816h(c[i][j], af[i], bf[j]);
        }
        __syncthreads();
    }

    #pragma unroll
    for (int j = 0; j < 4; j++) {
        const int col = col0 + n0 + j * 8 + (lane & 3) * 2;
        const float2 bb = *(const float2*)&bias[col];
        const float sc = (MODE == 1 && col < EMBED) ? 0.125f : 1.0f;
        #pragma unroll
        for (int i = 0; i < 2; i++) {
            const int r0 = row0 + m0 + i * 16 + (lane >> 2);
            float v0 = (c[i][j][0] + bb.x) * sc, v1 = (c[i][j][1] + bb.y) * sc;
            float v2 = (c[i][j][2] + bb.x) * sc, v3 = (c[i][j][3] + bb.y) * sc;
            if (MODE == 0) {
                *(float2*)&C[(size_t)r0 * N + col]       = make_float2(v0, v1);
                *(float2*)&C[(size_t)(r0 + 8) * N + col] = make_float2(v2, v3);
            } else {
                *(uint32_t*)&Chi[(size_t)r0 * N + col]       = pack2h(v0, v1);
                *(uint32_t*)&Chi[(size_t)(r0 + 8) * N + col] = pack2h(v2, v3);
            }
        }
    }
}

// -------------- TMA + fp16 flash attention -----------------------------------
// Q, K, V, P: single fp16. S = Q*K (1 term); O = P*V (1 term).
// 2-stage KV ring, 83 KB smem -> 2 CTAs/SM.
#define ASTG2 32768                           // K + V per stage
#define ASM_BYTES (1024 + 16384 + 2 * ASTG2)  // 82944

__global__ __launch_bounds__(256, 2)
void attn_tma(const __grid_constant__ CUtensorMap mQh,
              __nv_bfloat16* __restrict__ oh)
{
    extern __shared__ char smem[];
    __shared__ uint64_t mbar[3];   // [0]=Q, [1..2]=KV stages
    const uint32_t sb0 = (smem_u32(smem) + 1023) & ~1023u;
    const uint32_t sQh = sb0;
    const uint32_t sKV = sb0 + 16384;

    const int t = threadIdx.x, lane = t & 31, wid = t >> 5;
    const int qt = blockIdx.x, h = blockIdx.y, b = blockIdx.z;
    const int qrow = b * SEQ + qt * 128;

    uint32_t qb = smem_u32(&mbar[0]);
    uint32_t kb[2] = { smem_u32(&mbar[1]), smem_u32(&mbar[2]) };
    if (t == 0) { mb_init(qb, 1); mb_init(kb[0], 1); mb_init(kb[1], 1); }
    __syncthreads();

    auto issueKV = [&](int kt) {
        const int s = kt & 1;
        const uint32_t base = sKV + s * ASTG2;
        const int krow = b * SEQ + kt * 128;
        mb_expect(kb[s], ASTG2);
        tma2d(base,         &mQh, EMBED + h * HEAD_DIM,     krow, kb[s]);   // K
        tma2d(base + 16384, &mQh, 2 * EMBED + h * HEAD_DIM, krow, kb[s]);   // V
    };
    if (t == 0) {
        mb_expect(qb, 16384);
        tma2d(sQh, &mQh, h * HEAD_DIM, qrow, qb);
        issueKV(0); issueKV(1);
    }

    uint32_t qfh[4][4];
    MBWAIT(qb, 0);
    #pragma unroll
    for (int ks = 0; ks < 4; ks++) {
        const int r = wid * 16 + (lane & 15);
        const int ch = 2 * ks + (lane >> 4);
        const uint32_t qd = (uint32_t)(r * 128 + ((ch ^ (r & 7)) << 4));
        ldsm4(qfh[ks], sQh + qd);
    }

    float o[8][4] = {};
    float m_lo = -1e30f, m_hi = -1e30f, l_lo = 0.0f, l_hi = 0.0f;

    const int NKV = SEQ / 128;
    for (int kt = 0; kt < NKV; kt++) {
        const int s = kt & 1;
        MBWAIT(kb[s], (kt / 2) & 1);
        const uint32_t base = sKV + s * ASTG2;
        const uint32_t aKh = base, aVh = base + 16384;

        // ---- S = Q*K (1 term) ----
        float sfr[16][4] = {};
        #pragma unroll
        for (int ks = 0; ks < 4; ks++) {
            uint32_t kd[16];
            #pragma unroll
            for (int j = 0; j < 16; j++) {
                const int r = j * 8 + (lane & 7);
                const int ch = 2 * ks + ((lane >> 3) & 1);
                kd[j] = (uint32_t)(r * 128 + ((ch ^ (r & 7)) << 4));
            }
            uint32_t kf[16][2];
            #pragma unroll
            for (int j = 0; j < 16; j++) ldsm2(kf[j], aKh + kd[j]);
            #pragma unroll
            for (int j = 0; j < 16; j++) mma16816h(sfr[j], qfh[ks], kf[j]);
        }

        // ---- online softmax ----
        float tmax_lo = -1e30f, tmax_hi = -1e30f;
        #pragma unroll
        for (int j = 0; j < 16; j++) {
            tmax_lo = fmaxf(tmax_lo, fmaxf(sfr[j][0], sfr[j][1]));
            tmax_hi = fmaxf(tmax_hi, fmaxf(sfr[j][2], sfr[j][3]));
        }
        tmax_lo = fmaxf(tmax_lo, __shfl_xor_sync(0xffffffffu, tmax_lo, 1));
        tmax_lo = fmaxf(tmax_lo, __shfl_xor_sync(0xffffffffu, tmax_lo, 2));
        tmax_hi = fmaxf(tmax_hi, __shfl_xor_sync(0xffffffffu, tmax_hi, 1));
        tmax_hi = fmaxf(tmax_hi, __shfl_xor_sync(0xffffffffu, tmax_hi, 2));
        float mn_lo = fmaxf(m_lo, tmax_lo), mn_hi = fmaxf(m_hi, tmax_hi);
        float corr_lo = __expf(m_lo - mn_lo), corr_hi = __expf(m_hi - mn_hi);
        m_lo = mn_lo; m_hi = mn_hi;

        float sum_lo = 0.0f, sum_hi = 0.0f;
        #pragma unroll
        for (int j = 0; j < 16; j++) {
            sfr[j][0] = __expf(sfr[j][0] - m_lo); sfr[j][1] = __expf(sfr[j][1] - m_lo);
            sfr[j][2] = __expf(sfr[j][2] - m_hi); sfr[j][3] = __expf(sfr[j][3] - m_hi);
            sum_lo += sfr[j][0] + sfr[j][1];
            sum_hi += sfr[j][2] + sfr[j][3];
        }
        sum_lo += __shfl_xor_sync(0xffffffffu, sum_lo, 1);
        sum_lo += __shfl_xor_sync(0xffffffffu, sum_lo, 2);
        sum_hi += __shfl_xor_sync(0xffffffffu, sum_hi, 1);
        sum_hi += __shfl_xor_sync(0xffffffffu, sum_hi, 2);
        l_lo = l_lo * corr_lo + sum_lo;
        l_hi = l_hi * corr_hi + sum_hi;
        #pragma unroll
        for (int j = 0; j < 8; j++) {
            o[j][0] *= corr_lo; o[j][1] *= corr_lo;
            o[j][2] *= corr_hi; o[j][3] *= corr_hi;
        }

        // ---- O += P*V (1 term, P packed fp16) ----
        #pragma unroll
        for (int kk = 0; kk < 8; kk++) {
            uint32_t ph[4];
            ph[0] = pack2h(sfr[2*kk  ][0], sfr[2*kk  ][1]);
            ph[1] = pack2h(sfr[2*kk  ][2], sfr[2*kk  ][3]);
            ph[2] = pack2h(sfr[2*kk+1][0], sfr[2*kk+1][1]);
            ph[3] = pack2h(sfr[2*kk+1][2], sfr[2*kk+1][3]);

            const int r = kk * 16 + (lane & 15);
            uint32_t vf[8][2];
            #pragma unroll
            for (int j = 0; j < 8; j++)
                ldsm2t(vf[j], aVh + (uint32_t)(r * 128 + ((j ^ (r & 7)) << 4)));
            #pragma unroll
            for (int j = 0; j < 8; j++) mma16816h(o[j], ph, vf[j]);
        }
        __syncthreads();
        if (t == 0 && kt + 2 < NKV) issueKV(kt + 2);
    }

    // ---- epilogue: normalize + single fp16 out (proj GEMM A operand) ----
    const float inv_lo = 1.0f / l_lo, inv_hi = 1.0f / l_hi;
    const int r_lo = qt * 128 + wid * 16 + (lane >> 2);
    const size_t obase = (size_t)(b * SEQ) * EMBED + (size_t)h * HEAD_DIM;
    #pragma unroll
    for (int j = 0; j < 8; j++) {
        const int col = j * 8 + (lane & 3) * 2;
        *(uint32_t*)&oh[obase + (size_t)r_lo * EMBED + col] =
            pack2h(o[j][0] * inv_lo, o[j][1] * inv_lo);
        *(uint32_t*)&oh[obase + (size_t)(r_lo + 8) * EMBED + col] =
            pack2h(o[j][2] * inv_hi, o[j][3] * inv_hi);
    }
}

// ---------------------------------------------------------------------------
typedef CUresult (CUDAAPI *tmap_fn_t)(CUtensorMap*, CUtensorMapDataType, cuuint32_t,
    void*, const cuuint64_t*, const cuuint64_t*, const cuuint32_t*, const cuuint32_t*,
    CUtensorMapInterleave, CUtensorMapSwizzle, CUtensorMapL2promotion, CUtensorMapFloatOOBfill);

static void make_map(CUtensorMap* m, tmap_fn_t fn, void* base,
                     uint64_t cols, uint64_t rows)
{
    cuuint64_t dims[2]    = { cols, rows };
    cuuint64_t strides[1] = { cols * 2 };
    cuuint32_t box[2]     = { 64, 128 };
    cuuint32_t es[2]      = { 1, 1 };
    fn(m, CU_TENSOR_MAP_DATA_TYPE_BFLOAT16, 2, base, dims, strides, box, es,
       CU_TENSOR_MAP_INTERLEAVE_NONE, CU_TENSOR_MAP_SWIZZLE_128B,
       CU_TENSOR_MAP_L2_PROMOTION_L2_128B, CU_TENSOR_MAP_FLOAT_OOB_FILL_NONE);
}

extern "C" void kernel_launch(void* const* d_in, const int* in_sizes, int n_in,
                              void* d_out, int out_size)
{
    const float* x      = (const float*)d_in[0];
    const float* w_qkv  = (const float*)d_in[1];
    const float* b_qkv  = (const float*)d_in[2];
    const float* w_proj = (const float*)d_in[3];
    const float* b_proj = (const float*)d_in[4];
    float* out = (float*)d_out;

    __nv_bfloat16 *xh, *wqh, *wph, *qh, *ah;
    cudaGetSymbolAddress((void**)&xh, g_xh);
    cudaGetSymbolAddress((void**)&wqh, g_wqh);
    cudaGetSymbolAddress((void**)&wph, g_wph);
    cudaGetSymbolAddress((void**)&qh, g_qh);
    cudaGetSymbolAddress((void**)&ah, g_ah);

    tmap_fn_t fn = nullptr;
    cudaDriverEntryPointQueryResult qres;
    cudaGetDriverEntryPoint("cuTensorMapEncodeTiled", (void**)&fn,
                            cudaEnableDefault, &qres);

    static CUtensorMap mX, mWq, mWp, mQh, mA;
    make_map(&mX,  fn, xh,  EMBED,     MTOT);
    make_map(&mWq, fn, wqh, EMBED,     3 * EMBED);
    make_map(&mWp, fn, wph, EMBED,     EMBED);
    make_map(&mQh, fn, qh,  3 * EMBED, MTOT);
    make_map(&mA,  fn, ah,  EMBED,     MTOT);

    const int M = MTOT;
    cudaFuncSetAttribute(gemm_tma<0>, cudaFuncAttributeMaxDynamicSharedMemorySize, GSM);
    cudaFuncSetAttribute(gemm_tma<1>, cudaFuncAttributeMaxDynamicSharedMemorySize, GSM);
    cudaFuncSetAttribute(attn_tma,    cudaFuncAttributeMaxDynamicSharedMemorySize, ASM_BYTES);

    // fused fp32 -> fp16 converts (x, w_qkv, w_proj)
    {
        const int total = N4_X + N4_WQ + N4_WP;
        cvt3_kernel<<<(total + 255) / 256, 256>>>(x, xh, w_qkv, wqh, w_proj, wph);
    }

    // 1) QKV projection -> single fp16 (Q pre-scaled by 0.125)
    {
        dim3 g(3 * EMBED / 128, M / 128);
        gemm_tma<1><<<g, 512, GSM>>>(mX, mWq, b_qkv, nullptr, qh,
                                     M, 3 * EMBED, EMBED);
    }

    // 2) attention (fp16, 1-term QK / 1-term PV) -> single fp16
    {
        dim3 g(SEQ / 128, HEADS, BATCH);
        attn_tma<<<g, 256, ASM_BYTES>>>(mQh, ah);
    }

    // 3) proj GEMM -> fp32 out
    {
        dim3 g(EMBED / 128, M / 128);
        gemm_tma<0><<<g, 512, GSM>>>(mA, mWp, b_proj, out, nullptr,
                                     M, EMBED, EMBED);
    }
}